// round 5
// baseline (speedup 1.0000x reference)
#include <cuda_runtime.h>
#include <cuda_bf16.h>
#include <math.h>

// Problem dims
#define BB   256
#define SS   200
#define FF   10
#define EE   128
#define HH   256
#define G4H  1024   // 4*H
#define TT   100
#define P1_  512
#define P2_  128
#define MT   (BB*TT)   // 25600

// ---------------- scratch (static device globals; no runtime alloc) -------
__device__ float g_e[BB*SS*EE];
__device__ float g_xproj[(size_t)BB*SS*G4H];
__device__ float g_WihT[EE*G4H];
__device__ float g_WhhT[HH*G4H];
__device__ float g_bsum[G4H];
__device__ float g_hN[BB*HH];
__device__ float g_cN[BB*HH];
__device__ float g_hproj[BB*G4H];
__device__ float g_htgt[(size_t)MT*HH];
__device__ float g_z1[(size_t)MT*P1_];
__device__ float g_z2[(size_t)MT*P2_];

__device__ __forceinline__ float sigm(float x) { return 1.0f / (1.0f + expf(-x)); }

__device__ __forceinline__ unsigned f2tf32(float x) {
    unsigned u; asm("cvt.rna.tf32.f32 %0, %1;" : "=r"(u) : "f"(x)); return u;
}

__device__ __forceinline__ void mma8(float* d, const unsigned* a, const unsigned* b) {
    asm volatile(
        "mma.sync.aligned.m16n8k8.row.col.f32.tf32.tf32.f32 "
        "{%0,%1,%2,%3}, {%4,%5,%6,%7}, {%8,%9}, {%0,%1,%2,%3};\n"
        : "+f"(d[0]), "+f"(d[1]), "+f"(d[2]), "+f"(d[3])
        : "r"(a[0]), "r"(a[1]), "r"(a[2]), "r"(a[3]), "r"(b[0]), "r"(b[1]));
}

// ---------------- prep: transpose W_ih, W_hh to K-major; combine biases ----
__global__ void prep_kernel(const float* __restrict__ W_ih,
                            const float* __restrict__ W_hh,
                            const float* __restrict__ b_ih,
                            const float* __restrict__ b_hh) {
    int idx = blockIdx.x * blockDim.x + threadIdx.x;
    if (idx < EE * G4H) {
        int k = idx >> 10, j = idx & 1023;
        g_WihT[idx] = W_ih[j * EE + k];
    }
    if (idx < HH * G4H) {
        int k = idx >> 10, j = idx & 1023;
        g_WhhT[idx] = W_hh[j * HH + k];
    }
    if (idx < G4H) g_bsum[idx] = b_ih[idx] + b_hh[idx];
}

// ---------------- embedding gather + mean over F -------------------------
__global__ void gather_mean_kernel(const int* __restrict__ x,
                                   const float* __restrict__ emb) {
    int bs = blockIdx.x;
    int k  = threadIdx.x;
    const int* xi = x + bs * FF;
    float s = 0.f;
#pragma unroll
    for (int f = 0; f < FF; f++) s += emb[(size_t)xi[f] * EE + k];
    g_e[(size_t)bs * EE + k] = s * 0.1f;
}

// ---------------- tf32 tensor-core GEMM ----------------------------------
// C[MxN] = act(A[MxK] @ B[KxN] + bias). Row-major all. M%128==0, N%BN_==0,
// K%32==0. THREE=true => 3xTF32 split (fp32-accurate).
#define TBK 32
template<int BN_, bool THREE>
__global__ __launch_bounds__(256)
void mma_gemm(const float* __restrict__ A, const float* __restrict__ B,
              float* __restrict__ C, const float* __restrict__ bias,
              int M, int N, int K, int relu) {
    constexpr int BM_ = 128;
    constexpr int NC = THREE ? 2 : 1;          // hi (+ lo)
    constexpr int WN = BN_ / 2;                // warp n-tile (4x2 warp grid)
    constexpr int NF = WN / 8;                 // n-fragments per warp

    __shared__ unsigned As[NC][BM_][TBK + 1];
    __shared__ unsigned Bs[NC][TBK][BN_ + 1];

    int tid  = threadIdx.x;
    int lane = tid & 31, warp = tid >> 5;
    int wm = warp >> 1, wn = warp & 1;
    int gid = lane >> 2, tg = lane & 3;
    int m0 = blockIdx.y * BM_;
    int n0 = blockIdx.x * BN_;

    float acc[2][NF][4];
#pragma unroll
    for (int i = 0; i < 2; i++)
#pragma unroll
        for (int j = 0; j < NF; j++)
#pragma unroll
            for (int q = 0; q < 4; q++) acc[i][j][q] = 0.f;

    for (int k0 = 0; k0 < K; k0 += TBK) {
        // load A tile (float4 along K, convert to tf32 hi/lo)
#pragma unroll
        for (int idx = tid; idx < BM_ * TBK / 4; idx += 256) {
            int r = idx >> 3;
            int c = (idx & 7) * 4;
            float4 v = *(const float4*)&A[(size_t)(m0 + r) * K + k0 + c];
            float f[4] = {v.x, v.y, v.z, v.w};
#pragma unroll
            for (int j = 0; j < 4; j++) {
                unsigned hi = f2tf32(f[j]);
                As[0][r][c + j] = hi;
                if (THREE)
                    As[1][r][c + j] = f2tf32(f[j] - __uint_as_float(hi));
            }
        }
        // load B tile
#pragma unroll
        for (int idx = tid; idx < TBK * BN_ / 4; idx += 256) {
            int r = idx / (BN_ / 4);
            int c = (idx % (BN_ / 4)) * 4;
            float4 v = *(const float4*)&B[(size_t)(k0 + r) * N + n0 + c];
            float f[4] = {v.x, v.y, v.z, v.w};
#pragma unroll
            for (int j = 0; j < 4; j++) {
                unsigned hi = f2tf32(f[j]);
                Bs[0][r][c + j] = hi;
                if (THREE)
                    Bs[1][r][c + j] = f2tf32(f[j] - __uint_as_float(hi));
            }
        }
        __syncthreads();

#pragma unroll
        for (int ks = 0; ks < TBK / 8; ks++) {
            int kk = ks * 8;
            unsigned afr[NC][2][4];
#pragma unroll
            for (int mf = 0; mf < 2; mf++) {
                int mr = wm * 32 + mf * 16;
#pragma unroll
                for (int cc = 0; cc < NC; cc++) {
                    afr[cc][mf][0] = As[cc][mr + gid][kk + tg];
                    afr[cc][mf][1] = As[cc][mr + gid + 8][kk + tg];
                    afr[cc][mf][2] = As[cc][mr + gid][kk + tg + 4];
                    afr[cc][mf][3] = As[cc][mr + gid + 8][kk + tg + 4];
                }
            }
            unsigned bfr[NC][NF][2];
#pragma unroll
            for (int nf = 0; nf < NF; nf++) {
                int nc = wn * WN + nf * 8 + gid;
#pragma unroll
                for (int cc = 0; cc < NC; cc++) {
                    bfr[cc][nf][0] = Bs[cc][kk + tg][nc];
                    bfr[cc][nf][1] = Bs[cc][kk + tg + 4][nc];
                }
            }
#pragma unroll
            for (int mf = 0; mf < 2; mf++)
#pragma unroll
                for (int nf = 0; nf < NF; nf++) {
                    mma8(acc[mf][nf], afr[0][mf], bfr[0][nf]);
                    if (THREE) {
                        mma8(acc[mf][nf], afr[1][mf], bfr[0][nf]);
                        mma8(acc[mf][nf], afr[0][mf], bfr[1][nf]);
                    }
                }
        }
        __syncthreads();
    }

    // epilogue
#pragma unroll
    for (int mf = 0; mf < 2; mf++)
#pragma unroll
        for (int nf = 0; nf < NF; nf++) {
            int row = m0 + wm * 32 + mf * 16 + gid;
            int col = n0 + wn * WN + nf * 8 + tg * 2;
            float v0 = acc[mf][nf][0], v1 = acc[mf][nf][1];
            float v2 = acc[mf][nf][2], v3 = acc[mf][nf][3];
            if (bias) {
                float b0 = bias[col], b1 = bias[col + 1];
                v0 += b0; v1 += b1; v2 += b0; v3 += b1;
            }
            if (relu) {
                v0 = fmaxf(v0, 0.f); v1 = fmaxf(v1, 0.f);
                v2 = fmaxf(v2, 0.f); v3 = fmaxf(v3, 0.f);
            }
            float2 w0 = {v0, v1}, w1 = {v2, v3};
            *(float2*)&C[(size_t)row * N + col] = w0;
            *(float2*)&C[(size_t)(row + 8) * N + col] = w1;
        }
}

// ---------------- scalar fp32 SGEMM (small matrices only) ----------------
#define BM 64
#define BN 64
#define BKK 16
__global__ __launch_bounds__(256)
void sgemm_kernel(const float* __restrict__ A, const float* __restrict__ B,
                  float* __restrict__ C, const float* __restrict__ bias,
                  int M, int N, int K, int relu) {
    __shared__ float As[BKK][BM + 4];
    __shared__ float Bs[BKK][BN];
    int tid = threadIdx.x;
    int m0 = blockIdx.y * BM;
    int n0 = blockIdx.x * BN;
    int tx = tid & 15, ty = tid >> 4;

    int arow = tid >> 2;
    int acol = (tid & 3) * 4;
    int brow = tid >> 4;
    int bcol = (tid & 15) * 4;

    float acc[4][4] = {};
    for (int k0 = 0; k0 < K; k0 += BKK) {
        float4 av = *(const float4*)&A[(size_t)(m0 + arow) * K + k0 + acol];
        As[acol + 0][arow] = av.x;
        As[acol + 1][arow] = av.y;
        As[acol + 2][arow] = av.z;
        As[acol + 3][arow] = av.w;
        float4 bv = *(const float4*)&B[(size_t)(k0 + brow) * N + n0 + bcol];
        *(float4*)&Bs[brow][bcol] = bv;
        __syncthreads();
#pragma unroll
        for (int kk = 0; kk < BKK; kk++) {
            float a[4], b[4];
            *(float4*)a = *(const float4*)&As[kk][ty * 4];
            *(float4*)b = *(const float4*)&Bs[kk][tx * 4];
#pragma unroll
            for (int i = 0; i < 4; i++)
#pragma unroll
                for (int j = 0; j < 4; j++)
                    acc[i][j] += a[i] * b[j];
        }
        __syncthreads();
    }
#pragma unroll
    for (int i = 0; i < 4; i++) {
        int m = m0 + ty * 4 + i;
#pragma unroll
        for (int j = 0; j < 4; j++) {
            int n = n0 + tx * 4 + j;
            float v = acc[i][j];
            if (bias) v += bias[n];
            if (relu) v = fmaxf(v, 0.f);
            C[(size_t)m * N + n] = v;
        }
    }
}

// ---------------- LSTM recurrence over hist (100 steps) ------------------
#define LROWS 4
__global__ __launch_bounds__(256)
void lstm_kernel(const float* __restrict__ xproj,
                 const float* __restrict__ WhhT,
                 float* __restrict__ hN, float* __restrict__ cN) {
    int j = threadIdx.x;
    int b0 = blockIdx.x * LROWS;
    __shared__ float sh_h[LROWS][HH];
    float c[LROWS];
#pragma unroll
    for (int r = 0; r < LROWS; r++) { sh_h[r][j] = 0.f; c[r] = 0.f; }
    __syncthreads();

    for (int t = 0; t < TT; t++) {
        float ai[LROWS], af[LROWS], ag[LROWS], ao[LROWS];
#pragma unroll
        for (int r = 0; r < LROWS; r++) {
            size_t base = ((size_t)(b0 + r) * SS + t) * G4H + j;
            ai[r] = xproj[base];
            af[r] = xproj[base + 256];
            ag[r] = xproj[base + 512];
            ao[r] = xproj[base + 768];
        }
#pragma unroll 4
        for (int k = 0; k < HH; k++) {
            const float* w = &WhhT[(size_t)k * G4H + j];
            float wi = w[0], wf = w[256], wg = w[512], wo = w[768];
#pragma unroll
            for (int r = 0; r < LROWS; r++) {
                float hk = sh_h[r][k];
                ai[r] = fmaf(hk, wi, ai[r]);
                af[r] = fmaf(hk, wf, af[r]);
                ag[r] = fmaf(hk, wg, ag[r]);
                ao[r] = fmaf(hk, wo, ao[r]);
            }
        }
        float hnew[LROWS];
#pragma unroll
        for (int r = 0; r < LROWS; r++) {
            float cc = sigm(af[r]) * c[r] + sigm(ai[r]) * tanhf(ag[r]);
            c[r] = cc;
            hnew[r] = sigm(ao[r]) * tanhf(cc);
        }
        __syncthreads();
#pragma unroll
        for (int r = 0; r < LROWS; r++) sh_h[r][j] = hnew[r];
        __syncthreads();
    }
#pragma unroll
    for (int r = 0; r < LROWS; r++) {
        hN[(b0 + r) * HH + j] = sh_h[r][j];
        cN[(b0 + r) * HH + j] = c[r];
    }
}

// ---------------- tgt single-step LSTM (non-recurrent, parallel) ---------
__global__ __launch_bounds__(256)
void tgt_kernel(const float* __restrict__ xproj,
                const float* __restrict__ hproj,
                const float* __restrict__ cN) {
    int bt = blockIdx.x;
    int j  = threadIdx.x;
    int b = bt / TT, t = bt % TT;
    size_t base = ((size_t)b * SS + TT + t) * G4H + j;
    const float* hp = hproj + (size_t)b * G4H + j;
    float gi = xproj[base]       + hp[0];
    float gf = xproj[base + 256] + hp[256];
    float gg = xproj[base + 512] + hp[512];
    float go = xproj[base + 768] + hp[768];
    float cc = sigm(gf) * cN[b * HH + j] + sigm(gi) * tanhf(gg);
    g_htgt[(size_t)bt * HH + j] = sigm(go) * tanhf(cc);
}

// ---------------- final layer: out = sigmoid(z2 @ W3 + b3) ---------------
__global__ __launch_bounds__(128)
void final_kernel(const float* __restrict__ z2, const float* __restrict__ W3,
                  const float* __restrict__ b3, float* __restrict__ out) {
    int warp = threadIdx.x >> 5, lane = threadIdx.x & 31;
    int m = blockIdx.x * 4 + warp;
    if (m >= MT) return;
    const float* zr = z2 + (size_t)m * P2_;
    float s = 0.f;
#pragma unroll
    for (int q = 0; q < 4; q++) s = fmaf(zr[lane + q * 32], W3[lane + q * 32], s);
#pragma unroll
    for (int off = 16; off; off >>= 1) s += __shfl_xor_sync(0xFFFFFFFFu, s, off);
    if (lane == 0) out[m] = 1.f / (1.f + expf(-(s + b3[0])));
}

// ---------------- launch --------------------------------------------------
extern "C" void kernel_launch(void* const* d_in, const int* in_sizes, int n_in,
                              void* d_out, int out_size) {
    const int*   x    = (const int*)  d_in[0];
    const float* emb  = (const float*)d_in[1];
    const float* W_ih = (const float*)d_in[2];
    const float* W_hh = (const float*)d_in[3];
    const float* b_ih = (const float*)d_in[4];
    const float* b_hh = (const float*)d_in[5];
    const float* W1   = (const float*)d_in[6];
    const float* b1   = (const float*)d_in[7];
    const float* W2   = (const float*)d_in[8];
    const float* b2   = (const float*)d_in[9];
    const float* W3   = (const float*)d_in[10];
    const float* b3   = (const float*)d_in[11];
    float* out = (float*)d_out;

    float *e, *xproj, *WihT, *WhhT, *bsum, *hN, *cN, *hproj, *htgt, *z1, *z2;
    cudaGetSymbolAddress((void**)&e,     g_e);
    cudaGetSymbolAddress((void**)&xproj, g_xproj);
    cudaGetSymbolAddress((void**)&WihT,  g_WihT);
    cudaGetSymbolAddress((void**)&WhhT,  g_WhhT);
    cudaGetSymbolAddress((void**)&bsum,  g_bsum);
    cudaGetSymbolAddress((void**)&hN,    g_hN);
    cudaGetSymbolAddress((void**)&cN,    g_cN);
    cudaGetSymbolAddress((void**)&hproj, g_hproj);
    cudaGetSymbolAddress((void**)&htgt,  g_htgt);
    cudaGetSymbolAddress((void**)&z1,    g_z1);
    cudaGetSymbolAddress((void**)&z2,    g_z2);

    // 1) weight transposes + bias combine
    prep_kernel<<<(HH * G4H + 255) / 256, 256>>>(W_ih, W_hh, b_ih, b_hh);

    // 2) embedding gather + mean
    gather_mean_kernel<<<BB * SS, EE>>>(x, emb);

    // 3) xproj = e @ W_ihT + bsum  — 3xTF32 tensor-core GEMM (fp32-accurate,
    //    feeds the recurrence)
    {
        dim3 grid(G4H / 32, (BB * SS) / 128);
        mma_gemm<32, true><<<grid, 256>>>(e, WihT, xproj, bsum,
                                          BB * SS, G4H, EE, 0);
    }

    // 4) LSTM recurrence over hist (t = 0..99), exact fp32
    lstm_kernel<<<BB / LROWS, HH>>>(xproj, WhhT, hN, cN);

    // 5) hproj = hN @ W_hhT  (small; exact fp32)
    {
        dim3 grid(G4H / BN, BB / BM);
        sgemm_kernel<<<grid, 256>>>(hN, WhhT, hproj, nullptr, BB, G4H, HH, 0);
    }

    // 6) tgt one-shot LSTM step
    tgt_kernel<<<MT, HH>>>(xproj, hproj, cN);

    // 7) MLP — plain tf32 (post-recurrence, non-compounding error ~1e-4)
    {
        dim3 grid(P1_ / 64, MT / 128);
        mma_gemm<64, false><<<grid, 256>>>(htgt, W1, z1, b1, MT, P1_, HH, 1);
    }
    {
        dim3 grid(P2_ / 64, MT / 128);
        mma_gemm<64, false><<<grid, 256>>>(z1, W2, z2, b2, MT, P2_, P1_, 1);
    }

    // 8) final dot + sigmoid
    final_kernel<<<MT / 4, 128>>>(z2, W3, b3, out);

    (void)in_sizes; (void)n_in; (void)out_size;
}

// round 9
// speedup vs baseline: 1.4029x; 1.4029x over previous
#include <cuda_runtime.h>
#include <cuda_bf16.h>
#include <math.h>

// Problem dims
#define BB   256
#define SS   200
#define FF   10
#define EE   128
#define HH   256
#define G4H  1024   // 4*H
#define TT   100
#define P1_  512
#define P2_  128
#define MT   (BB*TT)   // 25600

// ---------------- scratch (static device globals; no runtime alloc) -------
__device__ float g_e[BB*SS*EE];
__device__ float g_xproj[(size_t)BB*SS*G4H];
__device__ float g_WihT[EE*G4H];
__device__ float g_WhhT[HH*G4H];
__device__ float4 g_Whh4[HH*HH];        // gate-interleaved: [k*256+j] = {i,f,g,o}
__device__ float g_bsum[G4H];
__device__ float g_hN[BB*HH];
__device__ float g_cN[BB*HH];
__device__ float g_hproj[BB*G4H];
__device__ float g_htgt[(size_t)MT*HH];
__device__ float g_z1[(size_t)MT*P1_];
__device__ float g_z2[(size_t)MT*P2_];

__device__ __forceinline__ float sigm(float x) { return 1.0f / (1.0f + expf(-x)); }

__device__ __forceinline__ __nv_bfloat16 bf_hi(float a) { return __float2bfloat16_rn(a); }
__device__ __forceinline__ __nv_bfloat16 bf_lo(float a, __nv_bfloat16 hi) {
    return __float2bfloat16_rn(a - __bfloat162float(hi));
}

__device__ __forceinline__ void mma16(float* d, const unsigned* a, const unsigned* b) {
    asm volatile(
        "mma.sync.aligned.m16n8k16.row.col.f32.bf16.bf16.f32 "
        "{%0,%1,%2,%3}, {%4,%5,%6,%7}, {%8,%9}, {%0,%1,%2,%3};\n"
        : "+f"(d[0]), "+f"(d[1]), "+f"(d[2]), "+f"(d[3])
        : "r"(a[0]), "r"(a[1]), "r"(a[2]), "r"(a[3]), "r"(b[0]), "r"(b[1]));
}

// ---------------- prep: transposes, packed LSTM weights, combined bias ----
__global__ void prep_kernel(const float* __restrict__ W_ih,
                            const float* __restrict__ W_hh,
                            const float* __restrict__ b_ih,
                            const float* __restrict__ b_hh) {
    int idx = blockIdx.x * blockDim.x + threadIdx.x;
    if (idx < EE * G4H) {
        int k = idx >> 10, j = idx & 1023;
        g_WihT[idx] = W_ih[j * EE + k];
    }
    if (idx < HH * G4H) {
        int k = idx >> 10, j = idx & 1023;
        g_WhhT[idx] = W_hh[j * HH + k];
    }
    if (idx < HH * HH) {   // packed: Whh4[k*256+j] = {w_i, w_f, w_g, w_o}(k,j)
        int k = idx >> 8, j = idx & 255;
        g_Whh4[idx] = make_float4(W_hh[(size_t)(j        ) * HH + k],
                                  W_hh[(size_t)(j + 256) * HH + k],
                                  W_hh[(size_t)(j + 512) * HH + k],
                                  W_hh[(size_t)(j + 768) * HH + k]);
    }
    if (idx < G4H) g_bsum[idx] = b_ih[idx] + b_hh[idx];
}

// ---------------- embedding gather + mean over F -------------------------
__global__ void gather_mean_kernel(const int* __restrict__ x,
                                   const float* __restrict__ emb) {
    int bs = blockIdx.x;
    int k  = threadIdx.x;
    const int* xi = x + bs * FF;
    float s = 0.f;
#pragma unroll
    for (int f = 0; f < FF; f++) s += emb[(size_t)xi[f] * EE + k];
    g_e[(size_t)bs * EE + k] = s * 0.1f;
}

// ---------------- bf16-split tensor-core GEMM ----------------------------
// C[MxN] = act(A[MxK] @ B[KxN] + bias), fp32 in/out.
// Split: acc = Ahi*Bhi + Ahi*Blo + Alo*Bhi  (~16-bit mantissa accuracy).
// Tile 128x64x32, 8 warps (4m x 2n), warp tile 32x32.
#define GBM 128
#define GBN 64
#define GBK 32
#define APAD 40   // row stride in bf16 elems: (20*gid+tg) mod 32 all-distinct
__global__ __launch_bounds__(256)
void bf16_gemm(const float* __restrict__ A, const float* __restrict__ B,
               float* __restrict__ C, const float* __restrict__ bias,
               int M, int N, int K, int relu) {
    __shared__ __align__(16) __nv_bfloat16 Ahi[GBM][APAD];
    __shared__ __align__(16) __nv_bfloat16 Alo[GBM][APAD];
    __shared__ __align__(16) __nv_bfloat16 Bthi[GBN][APAD];   // transposed [n][k]
    __shared__ __align__(16) __nv_bfloat16 Btlo[GBN][APAD];

    int tid  = threadIdx.x;
    int lane = tid & 31, warp = tid >> 5;
    int wm = warp >> 1, wn = warp & 1;         // 4 x 2 warp grid
    int gid = lane >> 2, tg = lane & 3;
    int m0 = blockIdx.y * GBM;
    int n0 = blockIdx.x * GBN;

    float acc[2][4][4];
#pragma unroll
    for (int i = 0; i < 2; i++)
#pragma unroll
        for (int j = 0; j < 4; j++)
#pragma unroll
            for (int q = 0; q < 4; q++) acc[i][j][q] = 0.f;

    for (int k0 = 0; k0 < K; k0 += GBK) {
        // ---- load A tile 128x32: 1024 float4s, 4 per thread ----
#pragma unroll
        for (int it = 0; it < 4; it++) {
            int idx = tid + it * 256;
            int r  = idx >> 3;
            int c4 = (idx & 7) * 4;
            float4 v = *(const float4*)&A[(size_t)(m0 + r) * K + k0 + c4];
            float f[4] = {v.x, v.y, v.z, v.w};
            __nv_bfloat16 h[4], l[4];
#pragma unroll
            for (int j = 0; j < 4; j++) { h[j] = bf_hi(f[j]); l[j] = bf_lo(f[j], h[j]); }
            unsigned h01 = (unsigned)__bfloat16_as_ushort(h[0]) |
                           ((unsigned)__bfloat16_as_ushort(h[1]) << 16);
            unsigned h23 = (unsigned)__bfloat16_as_ushort(h[2]) |
                           ((unsigned)__bfloat16_as_ushort(h[3]) << 16);
            unsigned l01 = (unsigned)__bfloat16_as_ushort(l[0]) |
                           ((unsigned)__bfloat16_as_ushort(l[1]) << 16);
            unsigned l23 = (unsigned)__bfloat16_as_ushort(l[2]) |
                           ((unsigned)__bfloat16_as_ushort(l[3]) << 16);
            *(uint2*)&Ahi[r][c4] = make_uint2(h01, h23);
            *(uint2*)&Alo[r][c4] = make_uint2(l01, l23);
        }
        // ---- load B tile 32x64 -> transposed [n][k]: 2 float4/thread ----
#pragma unroll
        for (int it = 0; it < 2; it++) {
            int idx = tid + it * 256;
            int kr  = idx >> 4;
            int nc4 = (idx & 15) * 4;
            float4 v = *(const float4*)&B[(size_t)(k0 + kr) * N + n0 + nc4];
            float f[4] = {v.x, v.y, v.z, v.w};
#pragma unroll
            for (int j = 0; j < 4; j++) {
                __nv_bfloat16 h = bf_hi(f[j]);
                Bthi[nc4 + j][kr] = h;
                Btlo[nc4 + j][kr] = bf_lo(f[j], h);
            }
        }
        __syncthreads();

#pragma unroll
        for (int ks = 0; ks < 2; ks++) {       // two k16 steps per k-slab
            int kb = ks * 16;
            unsigned ah[2][4], al[2][4];
#pragma unroll
            for (int mf = 0; mf < 2; mf++) {
                int r0 = wm * 32 + mf * 16 + gid;
                ah[mf][0] = *(const unsigned*)&Ahi[r0    ][kb + 2 * tg];
                ah[mf][1] = *(const unsigned*)&Ahi[r0 + 8][kb + 2 * tg];
                ah[mf][2] = *(const unsigned*)&Ahi[r0    ][kb + 8 + 2 * tg];
                ah[mf][3] = *(const unsigned*)&Ahi[r0 + 8][kb + 8 + 2 * tg];
                al[mf][0] = *(const unsigned*)&Alo[r0    ][kb + 2 * tg];
                al[mf][1] = *(const unsigned*)&Alo[r0 + 8][kb + 2 * tg];
                al[mf][2] = *(const unsigned*)&Alo[r0    ][kb + 8 + 2 * tg];
                al[mf][3] = *(const unsigned*)&Alo[r0 + 8][kb + 8 + 2 * tg];
            }
            unsigned bh[4][2], bl[4][2];
#pragma unroll
            for (int nf = 0; nf < 4; nf++) {
                int n = wn * 32 + nf * 8 + gid;
                bh[nf][0] = *(const unsigned*)&Bthi[n][kb + 2 * tg];
                bh[nf][1] = *(const unsigned*)&Bthi[n][kb + 8 + 2 * tg];
                bl[nf][0] = *(const unsigned*)&Btlo[n][kb + 2 * tg];
                bl[nf][1] = *(const unsigned*)&Btlo[n][kb + 8 + 2 * tg];
            }
#pragma unroll
            for (int mf = 0; mf < 2; mf++)
#pragma unroll
                for (int nf = 0; nf < 4; nf++) {
                    mma16(acc[mf][nf], ah[mf], bh[nf]);
                    mma16(acc[mf][nf], ah[mf], bl[nf]);
                    mma16(acc[mf][nf], al[mf], bh[nf]);
                }
        }
        __syncthreads();
    }

    // ---- epilogue ----
#pragma unroll
    for (int mf = 0; mf < 2; mf++)
#pragma unroll
        for (int nf = 0; nf < 4; nf++) {
            int row = m0 + wm * 32 + mf * 16 + gid;
            int col = n0 + wn * 32 + nf * 8 + tg * 2;
            float v0 = acc[mf][nf][0], v1 = acc[mf][nf][1];
            float v2 = acc[mf][nf][2], v3 = acc[mf][nf][3];
            if (bias) {
                float b0 = bias[col], b1 = bias[col + 1];
                v0 += b0; v1 += b1; v2 += b0; v3 += b1;
            }
            if (relu) {
                v0 = fmaxf(v0, 0.f); v1 = fmaxf(v1, 0.f);
                v2 = fmaxf(v2, 0.f); v3 = fmaxf(v3, 0.f);
            }
            float2 w0 = {v0, v1}, w1 = {v2, v3};
            *(float2*)&C[(size_t)row * N + col] = w0;
            *(float2*)&C[(size_t)(row + 8) * N + col] = w1;
        }
}

// ---------------- scalar fp32 SGEMM (small matrices only) ----------------
#define BM 64
#define BN 64
#define BKK 16
__global__ __launch_bounds__(256)
void sgemm_kernel(const float* __restrict__ A, const float* __restrict__ B,
                  float* __restrict__ C, const float* __restrict__ bias,
                  int M, int N, int K, int relu) {
    __shared__ float As[BKK][BM + 4];
    __shared__ float Bs[BKK][BN];
    int tid = threadIdx.x;
    int m0 = blockIdx.y * BM;
    int n0 = blockIdx.x * BN;
    int tx = tid & 15, ty = tid >> 4;

    int arow = tid >> 2;
    int acol = (tid & 3) * 4;
    int brow = tid >> 4;
    int bcol = (tid & 15) * 4;

    float acc[4][4] = {};
    for (int k0 = 0; k0 < K; k0 += BKK) {
        float4 av = *(const float4*)&A[(size_t)(m0 + arow) * K + k0 + acol];
        As[acol + 0][arow] = av.x;
        As[acol + 1][arow] = av.y;
        As[acol + 2][arow] = av.z;
        As[acol + 3][arow] = av.w;
        float4 bv = *(const float4*)&B[(size_t)(k0 + brow) * N + n0 + bcol];
        *(float4*)&Bs[brow][bcol] = bv;
        __syncthreads();
#pragma unroll
        for (int kk = 0; kk < BKK; kk++) {
            float a[4], b[4];
            *(float4*)a = *(const float4*)&As[kk][ty * 4];
            *(float4*)b = *(const float4*)&Bs[kk][tx * 4];
#pragma unroll
            for (int i = 0; i < 4; i++)
#pragma unroll
                for (int j = 0; j < 4; j++)
                    acc[i][j] += a[i] * b[j];
        }
        __syncthreads();
    }
#pragma unroll
    for (int i = 0; i < 4; i++) {
        int m = m0 + ty * 4 + i;
#pragma unroll
        for (int j = 0; j < 4; j++) {
            int n = n0 + tx * 4 + j;
            float v = acc[i][j];
            if (bias) v += bias[n];
            if (relu) v = fmaxf(v, 0.f);
            C[(size_t)m * N + n] = v;
        }
    }
}

// ---------------- LSTM recurrence over hist (100 steps) ------------------
// 64 CTAs x 512 threads; 4 batch rows per CTA, 2 rows per thread.
// Bitwise-identical fp32 math to the original: each gate accumulator (r,j)
// is computed by ONE thread, sequentially over k=0..255, same fmaf order.
#define LROWS 4
__global__ __launch_bounds__(512)
void lstm_kernel(const float* __restrict__ xproj,
                 const float4* __restrict__ Whh4,
                 float* __restrict__ hN, float* __restrict__ cN) {
    int j    = threadIdx.x & 255;        // h column 0..255
    int half = threadIdx.x >> 8;         // 0 or 1 -> rows {0,1} or {2,3}
    int b0 = blockIdx.x * LROWS;
    __shared__ float sh_h[LROWS][HH];
    float c[2];
#pragma unroll
    for (int rr = 0; rr < 2; rr++) { sh_h[half * 2 + rr][j] = 0.f; c[rr] = 0.f; }
    __syncthreads();

    for (int t = 0; t < TT; t++) {
        float ai[2], af[2], ag[2], ao[2];
#pragma unroll
        for (int rr = 0; rr < 2; rr++) {
            int r = half * 2 + rr;
            size_t base = ((size_t)(b0 + r) * SS + t) * G4H + j;
            ai[rr] = xproj[base];
            af[rr] = xproj[base + 256];
            ag[rr] = xproj[base + 512];
            ao[rr] = xproj[base + 768];
        }
#pragma unroll 4
        for (int k = 0; k < HH; k++) {
            float4 w = Whh4[k * HH + j];
#pragma unroll
            for (int rr = 0; rr < 2; rr++) {
                float hk = sh_h[half * 2 + rr][k];
                ai[rr] = fmaf(hk, w.x, ai[rr]);
                af[rr] = fmaf(hk, w.y, af[rr]);
                ag[rr] = fmaf(hk, w.z, ag[rr]);
                ao[rr] = fmaf(hk, w.w, ao[rr]);
            }
        }
        float hnew[2];
#pragma unroll
        for (int rr = 0; rr < 2; rr++) {
            float cc = sigm(af[rr]) * c[rr] + sigm(ai[rr]) * tanhf(ag[rr]);
            c[rr] = cc;
            hnew[rr] = sigm(ao[rr]) * tanhf(cc);
        }
        __syncthreads();
#pragma unroll
        for (int rr = 0; rr < 2; rr++) sh_h[half * 2 + rr][j] = hnew[rr];
        __syncthreads();
    }
#pragma unroll
    for (int rr = 0; rr < 2; rr++) {
        int r = half * 2 + rr;
        hN[(b0 + r) * HH + j] = sh_h[r][j];
        cN[(b0 + r) * HH + j] = c[rr];
    }
}

// ---------------- tgt single-step LSTM (non-recurrent, parallel) ---------
__global__ __launch_bounds__(256)
void tgt_kernel(const float* __restrict__ xproj,
                const float* __restrict__ hproj,
                const float* __restrict__ cN) {
    int bt = blockIdx.x;
    int j  = threadIdx.x;
    int b = bt / TT, t = bt % TT;
    size_t base = ((size_t)b * SS + TT + t) * G4H + j;
    const float* hp = hproj + (size_t)b * G4H + j;
    float gi = xproj[base]       + hp[0];
    float gf = xproj[base + 256] + hp[256];
    float gg = xproj[base + 512] + hp[512];
    float go = xproj[base + 768] + hp[768];
    float cc = sigm(gf) * cN[b * HH + j] + sigm(gi) * tanhf(gg);
    g_htgt[(size_t)bt * HH + j] = sigm(go) * tanhf(cc);
}

// ---------------- final layer: out = sigmoid(z2 @ W3 + b3) ---------------
__global__ __launch_bounds__(128)
void final_kernel(const float* __restrict__ z2, const float* __restrict__ W3,
                  const float* __restrict__ b3, float* __restrict__ out) {
    int warp = threadIdx.x >> 5, lane = threadIdx.x & 31;
    int m = blockIdx.x * 4 + warp;
    if (m >= MT) return;
    const float* zr = z2 + (size_t)m * P2_;
    float s = 0.f;
#pragma unroll
    for (int q = 0; q < 4; q++) s = fmaf(zr[lane + q * 32], W3[lane + q * 32], s);
#pragma unroll
    for (int off = 16; off; off >>= 1) s += __shfl_xor_sync(0xFFFFFFFFu, s, off);
    if (lane == 0) out[m] = 1.f / (1.f + expf(-(s + b3[0])));
}

// ---------------- launch --------------------------------------------------
extern "C" void kernel_launch(void* const* d_in, const int* in_sizes, int n_in,
                              void* d_out, int out_size) {
    const int*   x    = (const int*)  d_in[0];
    const float* emb  = (const float*)d_in[1];
    const float* W_ih = (const float*)d_in[2];
    const float* W_hh = (const float*)d_in[3];
    const float* b_ih = (const float*)d_in[4];
    const float* b_hh = (const float*)d_in[5];
    const float* W1   = (const float*)d_in[6];
    const float* b1   = (const float*)d_in[7];
    const float* W2   = (const float*)d_in[8];
    const float* b2   = (const float*)d_in[9];
    const float* W3   = (const float*)d_in[10];
    const float* b3   = (const float*)d_in[11];
    float* out = (float*)d_out;

    float *e, *xproj, *WihT, *WhhT, *bsum, *hN, *cN, *hproj, *htgt, *z1, *z2;
    float4* Whh4;
    cudaGetSymbolAddress((void**)&e,     g_e);
    cudaGetSymbolAddress((void**)&xproj, g_xproj);
    cudaGetSymbolAddress((void**)&WihT,  g_WihT);
    cudaGetSymbolAddress((void**)&WhhT,  g_WhhT);
    cudaGetSymbolAddress((void**)&Whh4,  g_Whh4);
    cudaGetSymbolAddress((void**)&bsum,  g_bsum);
    cudaGetSymbolAddress((void**)&hN,    g_hN);
    cudaGetSymbolAddress((void**)&cN,    g_cN);
    cudaGetSymbolAddress((void**)&hproj, g_hproj);
    cudaGetSymbolAddress((void**)&htgt,  g_htgt);
    cudaGetSymbolAddress((void**)&z1,    g_z1);
    cudaGetSymbolAddress((void**)&z2,    g_z2);

    // 1) weight transposes + packed LSTM weights + bias combine
    prep_kernel<<<(HH * G4H + 255) / 256, 256>>>(W_ih, W_hh, b_ih, b_hh);

    // 2) embedding gather + mean
    gather_mean_kernel<<<BB * SS, EE>>>(x, emb);

    // 3) xproj = e @ W_ihT + bsum  — bf16-split tensor-core GEMM
    {
        dim3 grid(G4H / GBN, (BB * SS) / GBM);
        bf16_gemm<<<grid, 256>>>(e, WihT, xproj, bsum, BB * SS, G4H, EE, 0);
    }

    // 4) LSTM recurrence over hist (t = 0..99), exact fp32 (packed weights,
    //    512 threads/CTA for latency hiding)
    lstm_kernel<<<BB / LROWS, 512>>>(xproj, Whh4, hN, cN);

    // 5) hproj = hN @ W_hhT  (small; exact fp32)
    {
        dim3 grid(G4H / BN, BB / BM);
        sgemm_kernel<<<grid, 256>>>(hN, WhhT, hproj, nullptr, BB, G4H, HH, 0);
    }

    // 6) tgt one-shot LSTM step
    tgt_kernel<<<MT, HH>>>(xproj, hproj, cN);

    // 7) MLP — bf16-split tensor-core GEMMs
    {
        dim3 grid(P1_ / GBN, MT / GBM);
        bf16_gemm<<<grid, 256>>>(htgt, W1, z1, b1, MT, P1_, HH, 1);
    }
    {
        dim3 grid(P2_ / GBN, MT / GBM);
        bf16_gemm<<<grid, 256>>>(z1, W2, z2, b2, MT, P2_, P1_, 1);
    }

    // 8) final dot + sigmoid
    final_kernel<<<MT / 4, 128>>>(z2, W3, b3, out);

    (void)in_sizes; (void)n_in; (void)out_size;
}

// round 10
// speedup vs baseline: 1.5509x; 1.1055x over previous
#include <cuda_runtime.h>
#include <cuda_bf16.h>
#include <math.h>

// Problem dims
#define BB   256
#define SS   200
#define FF   10
#define EE   128
#define HH   256
#define G4H  1024   // 4*H
#define TT   100
#define P1_  512
#define P2_  128
#define MT   (BB*TT)   // 25600

// ---------------- scratch (static device globals; no runtime alloc) -------
__device__ float g_e[BB*SS*EE];
__device__ float g_xproj[(size_t)BB*SS*G4H];
__device__ float g_WihT[EE*G4H];
__device__ float g_WhhT[HH*G4H];
__device__ float4 g_Whh4[HH*HH];        // gate-interleaved: [k*256+j] = {i,f,g,o}
__device__ float g_bsum[G4H];
__device__ float g_hN[BB*HH];
__device__ float g_cN[BB*HH];
__device__ float g_hproj[BB*G4H];
__device__ float g_htgt[(size_t)MT*HH];
__device__ float g_z1[(size_t)MT*P1_];
__device__ float g_z2[(size_t)MT*P2_];

__device__ __forceinline__ float sigm(float x) { return 1.0f / (1.0f + expf(-x)); }

__device__ __forceinline__ __nv_bfloat16 bf_hi(float a) { return __float2bfloat16_rn(a); }
__device__ __forceinline__ __nv_bfloat16 bf_lo(float a, __nv_bfloat16 hi) {
    return __float2bfloat16_rn(a - __bfloat162float(hi));
}

__device__ __forceinline__ void mma16(float* d, const unsigned* a, const unsigned* b) {
    asm volatile(
        "mma.sync.aligned.m16n8k16.row.col.f32.bf16.bf16.f32 "
        "{%0,%1,%2,%3}, {%4,%5,%6,%7}, {%8,%9}, {%0,%1,%2,%3};\n"
        : "+f"(d[0]), "+f"(d[1]), "+f"(d[2]), "+f"(d[3])
        : "r"(a[0]), "r"(a[1]), "r"(a[2]), "r"(a[3]), "r"(b[0]), "r"(b[1]));
}

// ---------------- prep: transposes, packed LSTM weights, combined bias ----
__global__ void prep_kernel(const float* __restrict__ W_ih,
                            const float* __restrict__ W_hh,
                            const float* __restrict__ b_ih,
                            const float* __restrict__ b_hh) {
    int idx = blockIdx.x * blockDim.x + threadIdx.x;
    if (idx < EE * G4H) {
        int k = idx >> 10, j = idx & 1023;
        g_WihT[idx] = W_ih[j * EE + k];
    }
    if (idx < HH * G4H) {
        int k = idx >> 10, j = idx & 1023;
        g_WhhT[idx] = W_hh[j * HH + k];
    }
    if (idx < HH * HH) {   // packed: Whh4[k*256+j] = {w_i, w_f, w_g, w_o}(k,j)
        int k = idx >> 8, j = idx & 255;
        g_Whh4[idx] = make_float4(W_hh[(size_t)(j        ) * HH + k],
                                  W_hh[(size_t)(j + 256) * HH + k],
                                  W_hh[(size_t)(j + 512) * HH + k],
                                  W_hh[(size_t)(j + 768) * HH + k]);
    }
    if (idx < G4H) g_bsum[idx] = b_ih[idx] + b_hh[idx];
}

// ---------------- embedding gather + mean over F -------------------------
__global__ void gather_mean_kernel(const int* __restrict__ x,
                                   const float* __restrict__ emb) {
    int bs = blockIdx.x;
    int k  = threadIdx.x;
    const int* xi = x + bs * FF;
    float s = 0.f;
#pragma unroll
    for (int f = 0; f < FF; f++) s += emb[(size_t)xi[f] * EE + k];
    g_e[(size_t)bs * EE + k] = s * 0.1f;
}

// ---------------- bf16-split tensor-core GEMM ----------------------------
// (unchanged from R9 — measured-good: ~0.3 ms total, rel_err 8.8e-8)
#define GBM 128
#define GBN 64
#define GBK 32
#define APAD 40
__global__ __launch_bounds__(256)
void bf16_gemm(const float* __restrict__ A, const float* __restrict__ B,
               float* __restrict__ C, const float* __restrict__ bias,
               int M, int N, int K, int relu) {
    __shared__ __align__(16) __nv_bfloat16 Ahi[GBM][APAD];
    __shared__ __align__(16) __nv_bfloat16 Alo[GBM][APAD];
    __shared__ __align__(16) __nv_bfloat16 Bthi[GBN][APAD];
    __shared__ __align__(16) __nv_bfloat16 Btlo[GBN][APAD];

    int tid  = threadIdx.x;
    int lane = tid & 31, warp = tid >> 5;
    int wm = warp >> 1, wn = warp & 1;
    int gid = lane >> 2, tg = lane & 3;
    int m0 = blockIdx.y * GBM;
    int n0 = blockIdx.x * GBN;

    float acc[2][4][4];
#pragma unroll
    for (int i = 0; i < 2; i++)
#pragma unroll
        for (int j = 0; j < 4; j++)
#pragma unroll
            for (int q = 0; q < 4; q++) acc[i][j][q] = 0.f;

    for (int k0 = 0; k0 < K; k0 += GBK) {
#pragma unroll
        for (int it = 0; it < 4; it++) {
            int idx = tid + it * 256;
            int r  = idx >> 3;
            int c4 = (idx & 7) * 4;
            float4 v = *(const float4*)&A[(size_t)(m0 + r) * K + k0 + c4];
            float f[4] = {v.x, v.y, v.z, v.w};
            __nv_bfloat16 h[4], l[4];
#pragma unroll
            for (int j = 0; j < 4; j++) { h[j] = bf_hi(f[j]); l[j] = bf_lo(f[j], h[j]); }
            unsigned h01 = (unsigned)__bfloat16_as_ushort(h[0]) |
                           ((unsigned)__bfloat16_as_ushort(h[1]) << 16);
            unsigned h23 = (unsigned)__bfloat16_as_ushort(h[2]) |
                           ((unsigned)__bfloat16_as_ushort(h[3]) << 16);
            unsigned l01 = (unsigned)__bfloat16_as_ushort(l[0]) |
                           ((unsigned)__bfloat16_as_ushort(l[1]) << 16);
            unsigned l23 = (unsigned)__bfloat16_as_ushort(l[2]) |
                           ((unsigned)__bfloat16_as_ushort(l[3]) << 16);
            *(uint2*)&Ahi[r][c4] = make_uint2(h01, h23);
            *(uint2*)&Alo[r][c4] = make_uint2(l01, l23);
        }
#pragma unroll
        for (int it = 0; it < 2; it++) {
            int idx = tid + it * 256;
            int kr  = idx >> 4;
            int nc4 = (idx & 15) * 4;
            float4 v = *(const float4*)&B[(size_t)(k0 + kr) * N + n0 + nc4];
            float f[4] = {v.x, v.y, v.z, v.w};
#pragma unroll
            for (int j = 0; j < 4; j++) {
                __nv_bfloat16 h = bf_hi(f[j]);
                Bthi[nc4 + j][kr] = h;
                Btlo[nc4 + j][kr] = bf_lo(f[j], h);
            }
        }
        __syncthreads();

#pragma unroll
        for (int ks = 0; ks < 2; ks++) {
            int kb = ks * 16;
            unsigned ah[2][4], al[2][4];
#pragma unroll
            for (int mf = 0; mf < 2; mf++) {
                int r0 = wm * 32 + mf * 16 + gid;
                ah[mf][0] = *(const unsigned*)&Ahi[r0    ][kb + 2 * tg];
                ah[mf][1] = *(const unsigned*)&Ahi[r0 + 8][kb + 2 * tg];
                ah[mf][2] = *(const unsigned*)&Ahi[r0    ][kb + 8 + 2 * tg];
                ah[mf][3] = *(const unsigned*)&Ahi[r0 + 8][kb + 8 + 2 * tg];
                al[mf][0] = *(const unsigned*)&Alo[r0    ][kb + 2 * tg];
                al[mf][1] = *(const unsigned*)&Alo[r0 + 8][kb + 2 * tg];
                al[mf][2] = *(const unsigned*)&Alo[r0    ][kb + 8 + 2 * tg];
                al[mf][3] = *(const unsigned*)&Alo[r0 + 8][kb + 8 + 2 * tg];
            }
            unsigned bh[4][2], bl[4][2];
#pragma unroll
            for (int nf = 0; nf < 4; nf++) {
                int n = wn * 32 + nf * 8 + gid;
                bh[nf][0] = *(const unsigned*)&Bthi[n][kb + 2 * tg];
                bh[nf][1] = *(const unsigned*)&Bthi[n][kb + 8 + 2 * tg];
                bl[nf][0] = *(const unsigned*)&Btlo[n][kb + 2 * tg];
                bl[nf][1] = *(const unsigned*)&Btlo[n][kb + 8 + 2 * tg];
            }
#pragma unroll
            for (int mf = 0; mf < 2; mf++)
#pragma unroll
                for (int nf = 0; nf < 4; nf++) {
                    mma16(acc[mf][nf], ah[mf], bh[nf]);
                    mma16(acc[mf][nf], ah[mf], bl[nf]);
                    mma16(acc[mf][nf], al[mf], bh[nf]);
                }
        }
        __syncthreads();
    }

#pragma unroll
    for (int mf = 0; mf < 2; mf++)
#pragma unroll
        for (int nf = 0; nf < 4; nf++) {
            int row = m0 + wm * 32 + mf * 16 + gid;
            int col = n0 + wn * 32 + nf * 8 + tg * 2;
            float v0 = acc[mf][nf][0], v1 = acc[mf][nf][1];
            float v2 = acc[mf][nf][2], v3 = acc[mf][nf][3];
            if (bias) {
                float b0 = bias[col], b1 = bias[col + 1];
                v0 += b0; v1 += b1; v2 += b0; v3 += b1;
            }
            if (relu) {
                v0 = fmaxf(v0, 0.f); v1 = fmaxf(v1, 0.f);
                v2 = fmaxf(v2, 0.f); v3 = fmaxf(v3, 0.f);
            }
            float2 w0 = {v0, v1}, w1 = {v2, v3};
            *(float2*)&C[(size_t)row * N + col] = w0;
            *(float2*)&C[(size_t)(row + 8) * N + col] = w1;
        }
}

// ---------------- scalar fp32 SGEMM (small matrices only) ----------------
#define BM 64
#define BN 64
#define BKK 16
__global__ __launch_bounds__(256)
void sgemm_kernel(const float* __restrict__ A, const float* __restrict__ B,
                  float* __restrict__ C, const float* __restrict__ bias,
                  int M, int N, int K, int relu) {
    __shared__ float As[BKK][BM + 4];
    __shared__ float Bs[BKK][BN];
    int tid = threadIdx.x;
    int m0 = blockIdx.y * BM;
    int n0 = blockIdx.x * BN;
    int tx = tid & 15, ty = tid >> 4;

    int arow = tid >> 2;
    int acol = (tid & 3) * 4;
    int brow = tid >> 4;
    int bcol = (tid & 15) * 4;

    float acc[4][4] = {};
    for (int k0 = 0; k0 < K; k0 += BKK) {
        float4 av = *(const float4*)&A[(size_t)(m0 + arow) * K + k0 + acol];
        As[acol + 0][arow] = av.x;
        As[acol + 1][arow] = av.y;
        As[acol + 2][arow] = av.z;
        As[acol + 3][arow] = av.w;
        float4 bv = *(const float4*)&B[(size_t)(k0 + brow) * N + n0 + bcol];
        *(float4*)&Bs[brow][bcol] = bv;
        __syncthreads();
#pragma unroll
        for (int kk = 0; kk < BKK; kk++) {
            float a[4], b[4];
            *(float4*)a = *(const float4*)&As[kk][ty * 4];
            *(float4*)b = *(const float4*)&Bs[kk][tx * 4];
#pragma unroll
            for (int i = 0; i < 4; i++)
#pragma unroll
                for (int j = 0; j < 4; j++)
                    acc[i][j] += a[i] * b[j];
        }
        __syncthreads();
    }
#pragma unroll
    for (int i = 0; i < 4; i++) {
        int m = m0 + ty * 4 + i;
#pragma unroll
        for (int j = 0; j < 4; j++) {
            int n = n0 + tx * 4 + j;
            float v = acc[i][j];
            if (bias) v += bias[n];
            if (relu) v = fmaxf(v, 0.f);
            C[(size_t)m * N + n] = v;
        }
    }
}

// ---------------- LSTM recurrence v3 --------------------------------------
// 64 CTAs x 256 threads. Thread j owns h-column j for all 4 batch rows:
//  - w4[k][j] loaded ONCE per (k,j) (1 MB/CTA/step L2 traffic, minimal)
//  - register double-buffered w prefetch (blocks of 8 k) hides L2 latency
//  - h stored transposed in SMEM: sh_h[buf][k] = {h[k][r0..r3]} -> one
//    broadcast LDS.128 per k (was 4 scalar LDS)
//  - xproj loads hoisted to step start, added after the k-loop
#define LROWS 4
__global__ __launch_bounds__(256)
void lstm_kernel(const float* __restrict__ xproj,
                 const float4* __restrict__ Whh4,
                 float* __restrict__ hN, float* __restrict__ cN) {
    int j  = threadIdx.x;               // h column 0..255
    int b0 = blockIdx.x * LROWS;
    __shared__ float4 sh_h[2][HH];      // ping-pong, transposed [k] -> rows
    float c0 = 0.f, c1 = 0.f, c2 = 0.f, c3 = 0.f;
    sh_h[0][j] = make_float4(0.f, 0.f, 0.f, 0.f);
    __syncthreads();

    const float4* wp = Whh4 + j;        // w4[k][j] = wp[k*HH]
    int buf = 0;
    for (int t = 0; t < TT; t++) {
        // hoisted xproj loads — in flight during the whole k-loop
        float xi[4], xf[4], xg[4], xo[4];
#pragma unroll
        for (int r = 0; r < 4; r++) {
            size_t base = ((size_t)(b0 + r) * SS + t) * G4H + j;
            xi[r] = xproj[base];
            xf[r] = xproj[base + 256];
            xg[r] = xproj[base + 512];
            xo[r] = xproj[base + 768];
        }

        float ai[4] = {0.f,0.f,0.f,0.f}, af[4] = {0.f,0.f,0.f,0.f};
        float ag[4] = {0.f,0.f,0.f,0.f}, ao[4] = {0.f,0.f,0.f,0.f};
        const float4* hp = sh_h[buf];

        float4 wn[8];
#pragma unroll
        for (int u = 0; u < 8; u++) wn[u] = wp[u * HH];

#pragma unroll 1
        for (int k0 = 0; k0 < HH; k0 += 8) {
            float4 wc[8];
#pragma unroll
            for (int u = 0; u < 8; u++) wc[u] = wn[u];
            if (k0 + 8 < HH) {
#pragma unroll
                for (int u = 0; u < 8; u++) wn[u] = wp[(k0 + 8 + u) * HH];
            }
#pragma unroll
            for (int u = 0; u < 8; u++) {
                float4 h4 = hp[k0 + u];          // broadcast LDS.128
                ai[0] = fmaf(h4.x, wc[u].x, ai[0]);
                af[0] = fmaf(h4.x, wc[u].y, af[0]);
                ag[0] = fmaf(h4.x, wc[u].z, ag[0]);
                ao[0] = fmaf(h4.x, wc[u].w, ao[0]);
                ai[1] = fmaf(h4.y, wc[u].x, ai[1]);
                af[1] = fmaf(h4.y, wc[u].y, af[1]);
                ag[1] = fmaf(h4.y, wc[u].z, ag[1]);
                ao[1] = fmaf(h4.y, wc[u].w, ao[1]);
                ai[2] = fmaf(h4.z, wc[u].x, ai[2]);
                af[2] = fmaf(h4.z, wc[u].y, af[2]);
                ag[2] = fmaf(h4.z, wc[u].z, ag[2]);
                ao[2] = fmaf(h4.z, wc[u].w, ao[2]);
                ai[3] = fmaf(h4.w, wc[u].x, ai[3]);
                af[3] = fmaf(h4.w, wc[u].y, af[3]);
                ag[3] = fmaf(h4.w, wc[u].z, ag[3]);
                ao[3] = fmaf(h4.w, wc[u].w, ao[3]);
            }
        }

        float hv[4], cv[4] = {c0, c1, c2, c3};
#pragma unroll
        for (int r = 0; r < 4; r++) {
            float gi = ai[r] + xi[r];
            float gf = af[r] + xf[r];
            float gg = ag[r] + xg[r];
            float go = ao[r] + xo[r];
            float cc = sigm(gf) * cv[r] + sigm(gi) * tanhf(gg);
            cv[r] = cc;
            hv[r] = sigm(go) * tanhf(cc);
        }
        c0 = cv[0]; c1 = cv[1]; c2 = cv[2]; c3 = cv[3];

        sh_h[buf ^ 1][j] = make_float4(hv[0], hv[1], hv[2], hv[3]);
        __syncthreads();
        buf ^= 1;
    }

    float4 hf = sh_h[buf][j];
    hN[(b0 + 0) * HH + j] = hf.x;
    hN[(b0 + 1) * HH + j] = hf.y;
    hN[(b0 + 2) * HH + j] = hf.z;
    hN[(b0 + 3) * HH + j] = hf.w;
    cN[(b0 + 0) * HH + j] = c0;
    cN[(b0 + 1) * HH + j] = c1;
    cN[(b0 + 2) * HH + j] = c2;
    cN[(b0 + 3) * HH + j] = c3;
}

// ---------------- tgt single-step LSTM (non-recurrent, parallel) ---------
__global__ __launch_bounds__(256)
void tgt_kernel(const float* __restrict__ xproj,
                const float* __restrict__ hproj,
                const float* __restrict__ cN) {
    int bt = blockIdx.x;
    int j  = threadIdx.x;
    int b = bt / TT, t = bt % TT;
    size_t base = ((size_t)b * SS + TT + t) * G4H + j;
    const float* hp = hproj + (size_t)b * G4H + j;
    float gi = xproj[base]       + hp[0];
    float gf = xproj[base + 256] + hp[256];
    float gg = xproj[base + 512] + hp[512];
    float go = xproj[base + 768] + hp[768];
    float cc = sigm(gf) * cN[b * HH + j] + sigm(gi) * tanhf(gg);
    g_htgt[(size_t)bt * HH + j] = sigm(go) * tanhf(cc);
}

// ---------------- final layer: out = sigmoid(z2 @ W3 + b3) ---------------
__global__ __launch_bounds__(128)
void final_kernel(const float* __restrict__ z2, const float* __restrict__ W3,
                  const float* __restrict__ b3, float* __restrict__ out) {
    int warp = threadIdx.x >> 5, lane = threadIdx.x & 31;
    int m = blockIdx.x * 4 + warp;
    if (m >= MT) return;
    const float* zr = z2 + (size_t)m * P2_;
    float s = 0.f;
#pragma unroll
    for (int q = 0; q < 4; q++) s = fmaf(zr[lane + q * 32], W3[lane + q * 32], s);
#pragma unroll
    for (int off = 16; off; off >>= 1) s += __shfl_xor_sync(0xFFFFFFFFu, s, off);
    if (lane == 0) out[m] = 1.f / (1.f + expf(-(s + b3[0])));
}

// ---------------- launch --------------------------------------------------
extern "C" void kernel_launch(void* const* d_in, const int* in_sizes, int n_in,
                              void* d_out, int out_size) {
    const int*   x    = (const int*)  d_in[0];
    const float* emb  = (const float*)d_in[1];
    const float* W_ih = (const float*)d_in[2];
    const float* W_hh = (const float*)d_in[3];
    const float* b_ih = (const float*)d_in[4];
    const float* b_hh = (const float*)d_in[5];
    const float* W1   = (const float*)d_in[6];
    const float* b1   = (const float*)d_in[7];
    const float* W2   = (const float*)d_in[8];
    const float* b2   = (const float*)d_in[9];
    const float* W3   = (const float*)d_in[10];
    const float* b3   = (const float*)d_in[11];
    float* out = (float*)d_out;

    float *e, *xproj, *WihT, *WhhT, *bsum, *hN, *cN, *hproj, *htgt, *z1, *z2;
    float4* Whh4;
    cudaGetSymbolAddress((void**)&e,     g_e);
    cudaGetSymbolAddress((void**)&xproj, g_xproj);
    cudaGetSymbolAddress((void**)&WihT,  g_WihT);
    cudaGetSymbolAddress((void**)&WhhT,  g_WhhT);
    cudaGetSymbolAddress((void**)&Whh4,  g_Whh4);
    cudaGetSymbolAddress((void**)&bsum,  g_bsum);
    cudaGetSymbolAddress((void**)&hN,    g_hN);
    cudaGetSymbolAddress((void**)&cN,    g_cN);
    cudaGetSymbolAddress((void**)&hproj, g_hproj);
    cudaGetSymbolAddress((void**)&htgt,  g_htgt);
    cudaGetSymbolAddress((void**)&z1,    g_z1);
    cudaGetSymbolAddress((void**)&z2,    g_z2);

    // 1) weight transposes + packed LSTM weights + bias combine
    prep_kernel<<<(HH * G4H + 255) / 256, 256>>>(W_ih, W_hh, b_ih, b_hh);

    // 2) embedding gather + mean
    gather_mean_kernel<<<BB * SS, EE>>>(x, emb);

    // 3) xproj = e @ W_ihT + bsum  — bf16-split tensor-core GEMM
    {
        dim3 grid(G4H / GBN, (BB * SS) / GBM);
        bf16_gemm<<<grid, 256>>>(e, WihT, xproj, bsum, BB * SS, G4H, EE, 0);
    }

    // 4) LSTM recurrence v3 (register-pipelined weights, transposed h)
    lstm_kernel<<<BB / LROWS, 256>>>(xproj, Whh4, hN, cN);

    // 5) hproj = hN @ W_hhT  (small; exact fp32)
    {
        dim3 grid(G4H / BN, BB / BM);
        sgemm_kernel<<<grid, 256>>>(hN, WhhT, hproj, nullptr, BB, G4H, HH, 0);
    }

    // 6) tgt one-shot LSTM step
    tgt_kernel<<<MT, HH>>>(xproj, hproj, cN);

    // 7) MLP — bf16-split tensor-core GEMMs
    {
        dim3 grid(P1_ / GBN, MT / GBM);
        bf16_gemm<<<grid, 256>>>(htgt, W1, z1, b1, MT, P1_, HH, 1);
    }
    {
        dim3 grid(P2_ / GBN, MT / GBM);
        bf16_gemm<<<grid, 256>>>(z1, W2, z2, b2, MT, P2_, P1_, 1);
    }

    // 8) final dot + sigmoid
    final_kernel<<<MT / 4, 128>>>(z2, W3, b3, out);

    (void)in_sizes; (void)n_in; (void)out_size;
}

// round 12
// speedup vs baseline: 2.9544x; 1.9049x over previous
#include <cuda_runtime.h>
#include <cuda_bf16.h>
#include <cooperative_groups.h>
#include <math.h>

namespace cg = cooperative_groups;

// Problem dims
#define BB   256
#define SS   200
#define FF   10
#define EE   128
#define HH   256
#define G4H  1024   // 4*H
#define TT   100
#define P1_  512
#define P2_  128
#define MT   (BB*TT)   // 25600

// ---------------- scratch (static device globals; no runtime alloc) -------
__device__ float g_e[BB*SS*EE];
__device__ float g_xproj[(size_t)BB*SS*G4H];
__device__ float g_WihT[EE*G4H];
__device__ float g_WhhT[HH*G4H];
__device__ float4 g_Whh4[HH*HH];        // gate-interleaved: [k*256+j] = {i,f,g,o}
__device__ float g_bsum[G4H];
__device__ float g_hN[BB*HH];
__device__ float g_cN[BB*HH];
__device__ float g_hproj[BB*G4H];
__device__ float g_htgt[(size_t)MT*HH];
__device__ float g_z1[(size_t)MT*P1_];
__device__ float g_z2[(size_t)MT*P2_];

__device__ __forceinline__ float sigm(float x) { return 1.0f / (1.0f + expf(-x)); }

__device__ __forceinline__ __nv_bfloat16 bf_hi(float a) { return __float2bfloat16_rn(a); }
__device__ __forceinline__ __nv_bfloat16 bf_lo(float a, __nv_bfloat16 hi) {
    return __float2bfloat16_rn(a - __bfloat162float(hi));
}

__device__ __forceinline__ void mma16(float* d, const unsigned* a, const unsigned* b) {
    asm volatile(
        "mma.sync.aligned.m16n8k16.row.col.f32.bf16.bf16.f32 "
        "{%0,%1,%2,%3}, {%4,%5,%6,%7}, {%8,%9}, {%0,%1,%2,%3};\n"
        : "+f"(d[0]), "+f"(d[1]), "+f"(d[2]), "+f"(d[3])
        : "r"(a[0]), "r"(a[1]), "r"(a[2]), "r"(a[3]), "r"(b[0]), "r"(b[1]));
}

// ---------------- prep: transposes, packed LSTM weights, combined bias ----
__global__ void prep_kernel(const float* __restrict__ W_ih,
                            const float* __restrict__ W_hh,
                            const float* __restrict__ b_ih,
                            const float* __restrict__ b_hh) {
    int idx = blockIdx.x * blockDim.x + threadIdx.x;
    if (idx < EE * G4H) {
        int k = idx >> 10, j = idx & 1023;
        g_WihT[idx] = W_ih[j * EE + k];
    }
    if (idx < HH * G4H) {
        int k = idx >> 10, j = idx & 1023;
        g_WhhT[idx] = W_hh[j * HH + k];
    }
    if (idx < HH * HH) {   // packed: Whh4[k*256+j] = {w_i, w_f, w_g, w_o}(k,j)
        int k = idx >> 8, j = idx & 255;
        g_Whh4[idx] = make_float4(W_hh[(size_t)(j        ) * HH + k],
                                  W_hh[(size_t)(j + 256) * HH + k],
                                  W_hh[(size_t)(j + 512) * HH + k],
                                  W_hh[(size_t)(j + 768) * HH + k]);
    }
    if (idx < G4H) g_bsum[idx] = b_ih[idx] + b_hh[idx];
}

// ---------------- embedding gather + mean over F -------------------------
__global__ void gather_mean_kernel(const int* __restrict__ x,
                                   const float* __restrict__ emb) {
    int bs = blockIdx.x;
    int k  = threadIdx.x;
    const int* xi = x + bs * FF;
    float s = 0.f;
#pragma unroll
    for (int f = 0; f < FF; f++) s += emb[(size_t)xi[f] * EE + k];
    g_e[(size_t)bs * EE + k] = s * 0.1f;
}

// ---------------- bf16-split tensor-core GEMM (unchanged, measured good) --
#define GBM 128
#define GBN 64
#define GBK 32
#define APAD 40
__global__ __launch_bounds__(256)
void bf16_gemm(const float* __restrict__ A, const float* __restrict__ B,
               float* __restrict__ C, const float* __restrict__ bias,
               int M, int N, int K, int relu) {
    __shared__ __align__(16) __nv_bfloat16 Ahi[GBM][APAD];
    __shared__ __align__(16) __nv_bfloat16 Alo[GBM][APAD];
    __shared__ __align__(16) __nv_bfloat16 Bthi[GBN][APAD];
    __shared__ __align__(16) __nv_bfloat16 Btlo[GBN][APAD];

    int tid  = threadIdx.x;
    int lane = tid & 31, warp = tid >> 5;
    int wm = warp >> 1, wn = warp & 1;
    int gid = lane >> 2, tg = lane & 3;
    int m0 = blockIdx.y * GBM;
    int n0 = blockIdx.x * GBN;

    float acc[2][4][4];
#pragma unroll
    for (int i = 0; i < 2; i++)
#pragma unroll
        for (int j = 0; j < 4; j++)
#pragma unroll
            for (int q = 0; q < 4; q++) acc[i][j][q] = 0.f;

    for (int k0 = 0; k0 < K; k0 += GBK) {
#pragma unroll
        for (int it = 0; it < 4; it++) {
            int idx = tid + it * 256;
            int r  = idx >> 3;
            int c4 = (idx & 7) * 4;
            float4 v = *(const float4*)&A[(size_t)(m0 + r) * K + k0 + c4];
            float f[4] = {v.x, v.y, v.z, v.w};
            __nv_bfloat16 h[4], l[4];
#pragma unroll
            for (int j = 0; j < 4; j++) { h[j] = bf_hi(f[j]); l[j] = bf_lo(f[j], h[j]); }
            unsigned h01 = (unsigned)__bfloat16_as_ushort(h[0]) |
                           ((unsigned)__bfloat16_as_ushort(h[1]) << 16);
            unsigned h23 = (unsigned)__bfloat16_as_ushort(h[2]) |
                           ((unsigned)__bfloat16_as_ushort(h[3]) << 16);
            unsigned l01 = (unsigned)__bfloat16_as_ushort(l[0]) |
                           ((unsigned)__bfloat16_as_ushort(l[1]) << 16);
            unsigned l23 = (unsigned)__bfloat16_as_ushort(l[2]) |
                           ((unsigned)__bfloat16_as_ushort(l[3]) << 16);
            *(uint2*)&Ahi[r][c4] = make_uint2(h01, h23);
            *(uint2*)&Alo[r][c4] = make_uint2(l01, l23);
        }
#pragma unroll
        for (int it = 0; it < 2; it++) {
            int idx = tid + it * 256;
            int kr  = idx >> 4;
            int nc4 = (idx & 15) * 4;
            float4 v = *(const float4*)&B[(size_t)(k0 + kr) * N + n0 + nc4];
            float f[4] = {v.x, v.y, v.z, v.w};
#pragma unroll
            for (int j = 0; j < 4; j++) {
                __nv_bfloat16 h = bf_hi(f[j]);
                Bthi[nc4 + j][kr] = h;
                Btlo[nc4 + j][kr] = bf_lo(f[j], h);
            }
        }
        __syncthreads();

#pragma unroll
        for (int ks = 0; ks < 2; ks++) {
            int kb = ks * 16;
            unsigned ah[2][4], al[2][4];
#pragma unroll
            for (int mf = 0; mf < 2; mf++) {
                int r0 = wm * 32 + mf * 16 + gid;
                ah[mf][0] = *(const unsigned*)&Ahi[r0    ][kb + 2 * tg];
                ah[mf][1] = *(const unsigned*)&Ahi[r0 + 8][kb + 2 * tg];
                ah[mf][2] = *(const unsigned*)&Ahi[r0    ][kb + 8 + 2 * tg];
                ah[mf][3] = *(const unsigned*)&Ahi[r0 + 8][kb + 8 + 2 * tg];
                al[mf][0] = *(const unsigned*)&Alo[r0    ][kb + 2 * tg];
                al[mf][1] = *(const unsigned*)&Alo[r0 + 8][kb + 2 * tg];
                al[mf][2] = *(const unsigned*)&Alo[r0    ][kb + 8 + 2 * tg];
                al[mf][3] = *(const unsigned*)&Alo[r0 + 8][kb + 8 + 2 * tg];
            }
            unsigned bh[4][2], bl[4][2];
#pragma unroll
            for (int nf = 0; nf < 4; nf++) {
                int n = wn * 32 + nf * 8 + gid;
                bh[nf][0] = *(const unsigned*)&Bthi[n][kb + 2 * tg];
                bh[nf][1] = *(const unsigned*)&Bthi[n][kb + 8 + 2 * tg];
                bl[nf][0] = *(const unsigned*)&Btlo[n][kb + 2 * tg];
                bl[nf][1] = *(const unsigned*)&Btlo[n][kb + 8 + 2 * tg];
            }
#pragma unroll
            for (int mf = 0; mf < 2; mf++)
#pragma unroll
                for (int nf = 0; nf < 4; nf++) {
                    mma16(acc[mf][nf], ah[mf], bh[nf]);
                    mma16(acc[mf][nf], ah[mf], bl[nf]);
                    mma16(acc[mf][nf], al[mf], bh[nf]);
                }
        }
        __syncthreads();
    }

#pragma unroll
    for (int mf = 0; mf < 2; mf++)
#pragma unroll
        for (int nf = 0; nf < 4; nf++) {
            int row = m0 + wm * 32 + mf * 16 + gid;
            int col = n0 + wn * 32 + nf * 8 + tg * 2;
            float v0 = acc[mf][nf][0], v1 = acc[mf][nf][1];
            float v2 = acc[mf][nf][2], v3 = acc[mf][nf][3];
            if (bias) {
                float b0 = bias[col], b1 = bias[col + 1];
                v0 += b0; v1 += b1; v2 += b0; v3 += b1;
            }
            if (relu) {
                v0 = fmaxf(v0, 0.f); v1 = fmaxf(v1, 0.f);
                v2 = fmaxf(v2, 0.f); v3 = fmaxf(v3, 0.f);
            }
            float2 w0 = {v0, v1}, w1 = {v2, v3};
            *(float2*)&C[(size_t)row * N + col] = w0;
            *(float2*)&C[(size_t)(row + 8) * N + col] = w1;
        }
}

// ---------------- scalar fp32 SGEMM (small matrices only) ----------------
#define BM 64
#define BN 64
#define BKK 16
__global__ __launch_bounds__(256)
void sgemm_kernel(const float* __restrict__ A, const float* __restrict__ B,
                  float* __restrict__ C, const float* __restrict__ bias,
                  int M, int N, int K, int relu) {
    __shared__ float As[BKK][BM + 4];
    __shared__ float Bs[BKK][BN];
    int tid = threadIdx.x;
    int m0 = blockIdx.y * BM;
    int n0 = blockIdx.x * BN;
    int tx = tid & 15, ty = tid >> 4;

    int arow = tid >> 2;
    int acol = (tid & 3) * 4;
    int brow = tid >> 4;
    int bcol = (tid & 15) * 4;

    float acc[4][4] = {};
    for (int k0 = 0; k0 < K; k0 += BKK) {
        float4 av = *(const float4*)&A[(size_t)(m0 + arow) * K + k0 + acol];
        As[acol + 0][arow] = av.x;
        As[acol + 1][arow] = av.y;
        As[acol + 2][arow] = av.z;
        As[acol + 3][arow] = av.w;
        float4 bv = *(const float4*)&B[(size_t)(k0 + brow) * N + n0 + bcol];
        *(float4*)&Bs[brow][bcol] = bv;
        __syncthreads();
#pragma unroll
        for (int kk = 0; kk < BKK; kk++) {
            float a[4], b[4];
            *(float4*)a = *(const float4*)&As[kk][ty * 4];
            *(float4*)b = *(const float4*)&Bs[kk][tx * 4];
#pragma unroll
            for (int i = 0; i < 4; i++)
#pragma unroll
                for (int j = 0; j < 4; j++)
                    acc[i][j] += a[i] * b[j];
        }
        __syncthreads();
    }
#pragma unroll
    for (int i = 0; i < 4; i++) {
        int m = m0 + ty * 4 + i;
#pragma unroll
        for (int j = 0; j < 4; j++) {
            int n = n0 + tx * 4 + j;
            float v = acc[i][j];
            if (bias) v += bias[n];
            if (relu) v = fmaxf(v, 0.f);
            C[(size_t)m * N + n] = v;
        }
    }
}

// ---------------- LSTM recurrence v4b: 2-CTA cluster j-split --------------
// Same design as v4 (R11) but ALL cluster mechanics via cooperative_groups:
// this_cluster() / map_shared_rank() / cluster.sync(). No hand-written PTX.
#define LROWS 4
__global__ __launch_bounds__(256) __cluster_dims__(2, 1, 1)
void lstm_kernel(const float* __restrict__ xproj,
                 const float4* __restrict__ Whh4,
                 float* __restrict__ hN, float* __restrict__ cN) {
    cg::cluster_group cluster = cg::this_cluster();
    int tid = threadIdx.x;
    int jl = tid & 127;                 // local gate column
    int kh = tid >> 7;                  // k-half 0/1
    unsigned rank = cluster.block_rank();
    int gj = (int)rank * 128 + jl;      // global gate/h column
    int b0 = (blockIdx.x >> 1) * LROWS; // batch group

    __shared__ float4 sh_h[2][HH];      // ping-pong full h (rows packed), 8KB
    __shared__ float4 sh_p[LROWS][128]; // kh=1 partials, 8KB

    sh_h[0][tid] = make_float4(0.f, 0.f, 0.f, 0.f);
    sh_h[1][tid] = make_float4(0.f, 0.f, 0.f, 0.f);
    __syncthreads();
    cluster.sync();

    // peer CTA's sh_h (generic pointer into DSMEM window)
    float4* peer_h = cluster.map_shared_rank(&sh_h[0][0], rank ^ 1u);

    const float4* wp = Whh4 + (size_t)(kh * 128) * HH + gj;  // wp[k*HH]
    float c0 = 0.f, c1 = 0.f, c2 = 0.f, c3 = 0.f;

    int buf = 0;
    for (int t = 0; t < TT; t++) {
        float xg0[4], xg1[4], xg2[4], xg3[4];
        if (kh == 0) {
#pragma unroll
            for (int r = 0; r < 4; r++) {
                size_t base = ((size_t)(b0 + r) * SS + t) * G4H + gj;
                xg0[r] = xproj[base];
                xg1[r] = xproj[base + 256];
                xg2[r] = xproj[base + 512];
                xg3[r] = xproj[base + 768];
            }
        }

        float ai[4] = {0.f,0.f,0.f,0.f}, af[4] = {0.f,0.f,0.f,0.f};
        float ag[4] = {0.f,0.f,0.f,0.f}, ao[4] = {0.f,0.f,0.f,0.f};
        const float4* hp = &sh_h[buf][kh * 128];

        float4 wn[8];
#pragma unroll
        for (int u = 0; u < 8; u++) wn[u] = wp[u * HH];

#pragma unroll 1
        for (int k0 = 0; k0 < 128; k0 += 8) {
            float4 wc[8];
#pragma unroll
            for (int u = 0; u < 8; u++) wc[u] = wn[u];
            if (k0 + 8 < 128) {
#pragma unroll
                for (int u = 0; u < 8; u++) wn[u] = wp[(k0 + 8 + u) * HH];
            }
#pragma unroll
            for (int u = 0; u < 8; u++) {
                float4 h4 = hp[k0 + u];          // broadcast LDS.128
                ai[0] = fmaf(h4.x, wc[u].x, ai[0]);
                af[0] = fmaf(h4.x, wc[u].y, af[0]);
                ag[0] = fmaf(h4.x, wc[u].z, ag[0]);
                ao[0] = fmaf(h4.x, wc[u].w, ao[0]);
                ai[1] = fmaf(h4.y, wc[u].x, ai[1]);
                af[1] = fmaf(h4.y, wc[u].y, af[1]);
                ag[1] = fmaf(h4.y, wc[u].z, ag[1]);
                ao[1] = fmaf(h4.y, wc[u].w, ao[1]);
                ai[2] = fmaf(h4.z, wc[u].x, ai[2]);
                af[2] = fmaf(h4.z, wc[u].y, af[2]);
                ag[2] = fmaf(h4.z, wc[u].z, ag[2]);
                ao[2] = fmaf(h4.z, wc[u].w, ao[2]);
                ai[3] = fmaf(h4.w, wc[u].x, ai[3]);
                af[3] = fmaf(h4.w, wc[u].y, af[3]);
                ag[3] = fmaf(h4.w, wc[u].z, ag[3]);
                ao[3] = fmaf(h4.w, wc[u].w, ao[3]);
            }
        }

        // kh=1 publishes partials
        if (kh == 1) {
#pragma unroll
            for (int r = 0; r < 4; r++)
                sh_p[r][jl] = make_float4(ai[r], af[r], ag[r], ao[r]);
        }
        __syncthreads();

        if (kh == 0) {
            float hv[4], cv[4] = {c0, c1, c2, c3};
#pragma unroll
            for (int r = 0; r < 4; r++) {
                float4 p = sh_p[r][jl];
                float gi = (ai[r] + p.x) + xg0[r];
                float gf = (af[r] + p.y) + xg1[r];
                float gg = (ag[r] + p.z) + xg2[r];
                float go = (ao[r] + p.w) + xg3[r];
                float cc = sigm(gf) * cv[r] + sigm(gi) * tanhf(gg);
                cv[r] = cc;
                hv[r] = sigm(go) * tanhf(cc);
            }
            c0 = cv[0]; c1 = cv[1]; c2 = cv[2]; c3 = cv[3];
            float4 hq = make_float4(hv[0], hv[1], hv[2], hv[3]);
            sh_h[buf ^ 1][gj] = hq;              // own copy
            peer_h[(buf ^ 1) * HH + gj] = hq;    // peer copy (DSMEM)
        }

        cluster.sync();
        buf ^= 1;
    }

    if (kh == 0) {
        float4 hf = sh_h[buf][gj];
        hN[(b0 + 0) * HH + gj] = hf.x;
        hN[(b0 + 1) * HH + gj] = hf.y;
        hN[(b0 + 2) * HH + gj] = hf.z;
        hN[(b0 + 3) * HH + gj] = hf.w;
        cN[(b0 + 0) * HH + gj] = c0;
        cN[(b0 + 1) * HH + gj] = c1;
        cN[(b0 + 2) * HH + gj] = c2;
        cN[(b0 + 3) * HH + gj] = c3;
    }
}

// ---------------- tgt single-step LSTM (non-recurrent, parallel) ---------
__global__ __launch_bounds__(256)
void tgt_kernel(const float* __restrict__ xproj,
                const float* __restrict__ hproj,
                const float* __restrict__ cN) {
    int bt = blockIdx.x;
    int j  = threadIdx.x;
    int b = bt / TT, t = bt % TT;
    size_t base = ((size_t)b * SS + TT + t) * G4H + j;
    const float* hp = hproj + (size_t)b * G4H + j;
    float gi = xproj[base]       + hp[0];
    float gf = xproj[base + 256] + hp[256];
    float gg = xproj[base + 512] + hp[512];
    float go = xproj[base + 768] + hp[768];
    float cc = sigm(gf) * cN[b * HH + j] + sigm(gi) * tanhf(gg);
    g_htgt[(size_t)bt * HH + j] = sigm(go) * tanhf(cc);
}

// ---------------- final layer: out = sigmoid(z2 @ W3 + b3) ---------------
__global__ __launch_bounds__(128)
void final_kernel(const float* __restrict__ z2, const float* __restrict__ W3,
                  const float* __restrict__ b3, float* __restrict__ out) {
    int warp = threadIdx.x >> 5, lane = threadIdx.x & 31;
    int m = blockIdx.x * 4 + warp;
    if (m >= MT) return;
    const float* zr = z2 + (size_t)m * P2_;
    float s = 0.f;
#pragma unroll
    for (int q = 0; q < 4; q++) s = fmaf(zr[lane + q * 32], W3[lane + q * 32], s);
#pragma unroll
    for (int off = 16; off; off >>= 1) s += __shfl_xor_sync(0xFFFFFFFFu, s, off);
    if (lane == 0) out[m] = 1.f / (1.f + expf(-(s + b3[0])));
}

// ---------------- launch --------------------------------------------------
extern "C" void kernel_launch(void* const* d_in, const int* in_sizes, int n_in,
                              void* d_out, int out_size) {
    const int*   x    = (const int*)  d_in[0];
    const float* emb  = (const float*)d_in[1];
    const float* W_ih = (const float*)d_in[2];
    const float* W_hh = (const float*)d_in[3];
    const float* b_ih = (const float*)d_in[4];
    const float* b_hh = (const float*)d_in[5];
    const float* W1   = (const float*)d_in[6];
    const float* b1   = (const float*)d_in[7];
    const float* W2   = (const float*)d_in[8];
    const float* b2   = (const float*)d_in[9];
    const float* W3   = (const float*)d_in[10];
    const float* b3   = (const float*)d_in[11];
    float* out = (float*)d_out;

    float *e, *xproj, *WihT, *WhhT, *bsum, *hN, *cN, *hproj, *htgt, *z1, *z2;
    float4* Whh4;
    cudaGetSymbolAddress((void**)&e,     g_e);
    cudaGetSymbolAddress((void**)&xproj, g_xproj);
    cudaGetSymbolAddress((void**)&WihT,  g_WihT);
    cudaGetSymbolAddress((void**)&WhhT,  g_WhhT);
    cudaGetSymbolAddress((void**)&Whh4,  g_Whh4);
    cudaGetSymbolAddress((void**)&bsum,  g_bsum);
    cudaGetSymbolAddress((void**)&hN,    g_hN);
    cudaGetSymbolAddress((void**)&cN,    g_cN);
    cudaGetSymbolAddress((void**)&hproj, g_hproj);
    cudaGetSymbolAddress((void**)&htgt,  g_htgt);
    cudaGetSymbolAddress((void**)&z1,    g_z1);
    cudaGetSymbolAddress((void**)&z2,    g_z2);

    // 1) weight transposes + packed LSTM weights + bias combine
    prep_kernel<<<(HH * G4H + 255) / 256, 256>>>(W_ih, W_hh, b_ih, b_hh);

    // 2) embedding gather + mean
    gather_mean_kernel<<<BB * SS, EE>>>(x, emb);

    // 3) xproj = e @ W_ihT + bsum  — bf16-split tensor-core GEMM
    {
        dim3 grid(G4H / GBN, (BB * SS) / GBM);
        bf16_gemm<<<grid, 256>>>(e, WihT, xproj, bsum, BB * SS, G4H, EE, 0);
    }

    // 4) LSTM recurrence v4b: 128 CTAs, clusters of 2 (cooperative_groups)
    lstm_kernel<<<(BB / LROWS) * 2, 256>>>(xproj, Whh4, hN, cN);

    // 5) hproj = hN @ W_hhT  (small; exact fp32)
    {
        dim3 grid(G4H / BN, BB / BM);
        sgemm_kernel<<<grid, 256>>>(hN, WhhT, hproj, nullptr, BB, G4H, HH, 0);
    }

    // 6) tgt one-shot LSTM step
    tgt_kernel<<<MT, HH>>>(xproj, hproj, cN);

    // 7) MLP — bf16-split tensor-core GEMMs
    {
        dim3 grid(P1_ / GBN, MT / GBM);
        bf16_gemm<<<grid, 256>>>(htgt, W1, z1, b1, MT, P1_, HH, 1);
    }
    {
        dim3 grid(P2_ / GBN, MT / GBM);
        bf16_gemm<<<grid, 256>>>(z1, W2, z2, b2, MT, P2_, P1_, 1);
    }

    // 8) final dot + sigmoid
    final_kernel<<<MT / 4, 128>>>(z2, W3, b3, out);

    (void)in_sizes; (void)n_in; (void)out_size;
}

// round 17
// speedup vs baseline: 3.3841x; 1.1455x over previous
#include <cuda_runtime.h>
#include <cuda_bf16.h>
#include <cooperative_groups.h>
#include <math.h>

namespace cg = cooperative_groups;

// Problem dims
#define BB   256
#define SS   200
#define FF   10
#define EE   128
#define HH   256
#define G4H  1024   // 4*H
#define TT   100
#define P1_  512
#define P2_  128
#define MT   (BB*TT)   // 25600

// ---------------- scratch (static device globals; no runtime alloc) -------
__device__ float g_e[BB*SS*EE];
__device__ float g_xproj[(size_t)BB*SS*G4H];
__device__ float g_WihT[EE*G4H];
__device__ float g_WhhT[HH*G4H];
__device__ float4 g_Whh4[HH*HH];        // gate-interleaved: [k*256+j] = {i,f,g,o}
__device__ float g_bsum[G4H];
__device__ float g_hN[BB*HH];
__device__ float g_cN[BB*HH];
__device__ float g_hproj[BB*G4H];
__device__ float g_htgt[(size_t)MT*HH];
__device__ float g_z1[(size_t)MT*P1_];
__device__ float g_z2[(size_t)MT*P2_];

__device__ __forceinline__ float sigm(float x) { return 1.0f / (1.0f + expf(-x)); }

__device__ __forceinline__ __nv_bfloat16 bf_hi(float a) { return __float2bfloat16_rn(a); }
__device__ __forceinline__ __nv_bfloat16 bf_lo(float a, __nv_bfloat16 hi) {
    return __float2bfloat16_rn(a - __bfloat162float(hi));
}

__device__ __forceinline__ void mma16(float* d, const unsigned* a, const unsigned* b) {
    asm volatile(
        "mma.sync.aligned.m16n8k16.row.col.f32.bf16.bf16.f32 "
        "{%0,%1,%2,%3}, {%4,%5,%6,%7}, {%8,%9}, {%0,%1,%2,%3};\n"
        : "+f"(d[0]), "+f"(d[1]), "+f"(d[2]), "+f"(d[3])
        : "r"(a[0]), "r"(a[1]), "r"(a[2]), "r"(a[3]), "r"(b[0]), "r"(b[1]));
}

// ---------------- prep: transposes, packed LSTM weights, combined bias ----
__global__ void prep_kernel(const float* __restrict__ W_ih,
                            const float* __restrict__ W_hh,
                            const float* __restrict__ b_ih,
                            const float* __restrict__ b_hh) {
    int idx = blockIdx.x * blockDim.x + threadIdx.x;
    if (idx < EE * G4H) {
        int k = idx >> 10, j = idx & 1023;
        g_WihT[idx] = W_ih[j * EE + k];
    }
    if (idx < HH * G4H) {
        int k = idx >> 10, j = idx & 1023;
        g_WhhT[idx] = W_hh[j * HH + k];
    }
    if (idx < HH * HH) {   // packed: Whh4[k*256+j] = {w_i, w_f, w_g, w_o}(k,j)
        int k = idx >> 8, j = idx & 255;
        g_Whh4[idx] = make_float4(W_hh[(size_t)(j        ) * HH + k],
                                  W_hh[(size_t)(j + 256) * HH + k],
                                  W_hh[(size_t)(j + 512) * HH + k],
                                  W_hh[(size_t)(j + 768) * HH + k]);
    }
    if (idx < G4H) g_bsum[idx] = b_ih[idx] + b_hh[idx];
}

// ---------------- embedding gather + mean over F -------------------------
__global__ void gather_mean_kernel(const int* __restrict__ x,
                                   const float* __restrict__ emb) {
    int bs = blockIdx.x;
    int k  = threadIdx.x;
    const int* xi = x + bs * FF;
    float s = 0.f;
#pragma unroll
    for (int f = 0; f < FF; f++) s += emb[(size_t)xi[f] * EE + k];
    g_e[(size_t)bs * EE + k] = s * 0.1f;
}

// ---------------- bf16-split tensor-core GEMM (unchanged, measured good) --
#define GBM 128
#define GBN 64
#define GBK 32
#define APAD 40
__global__ __launch_bounds__(256)
void bf16_gemm(const float* __restrict__ A, const float* __restrict__ B,
               float* __restrict__ C, const float* __restrict__ bias,
               int M, int N, int K, int relu) {
    __shared__ __align__(16) __nv_bfloat16 Ahi[GBM][APAD];
    __shared__ __align__(16) __nv_bfloat16 Alo[GBM][APAD];
    __shared__ __align__(16) __nv_bfloat16 Bthi[GBN][APAD];
    __shared__ __align__(16) __nv_bfloat16 Btlo[GBN][APAD];

    int tid  = threadIdx.x;
    int lane = tid & 31, warp = tid >> 5;
    int wm = warp >> 1, wn = warp & 1;
    int gid = lane >> 2, tg = lane & 3;
    int m0 = blockIdx.y * GBM;
    int n0 = blockIdx.x * GBN;

    float acc[2][4][4];
#pragma unroll
    for (int i = 0; i < 2; i++)
#pragma unroll
        for (int j = 0; j < 4; j++)
#pragma unroll
            for (int q = 0; q < 4; q++) acc[i][j][q] = 0.f;

    for (int k0 = 0; k0 < K; k0 += GBK) {
#pragma unroll
        for (int it = 0; it < 4; it++) {
            int idx = tid + it * 256;
            int r  = idx >> 3;
            int c4 = (idx & 7) * 4;
            float4 v = *(const float4*)&A[(size_t)(m0 + r) * K + k0 + c4];
            float f[4] = {v.x, v.y, v.z, v.w};
            __nv_bfloat16 h[4], l[4];
#pragma unroll
            for (int j = 0; j < 4; j++) { h[j] = bf_hi(f[j]); l[j] = bf_lo(f[j], h[j]); }
            unsigned h01 = (unsigned)__bfloat16_as_ushort(h[0]) |
                           ((unsigned)__bfloat16_as_ushort(h[1]) << 16);
            unsigned h23 = (unsigned)__bfloat16_as_ushort(h[2]) |
                           ((unsigned)__bfloat16_as_ushort(h[3]) << 16);
            unsigned l01 = (unsigned)__bfloat16_as_ushort(l[0]) |
                           ((unsigned)__bfloat16_as_ushort(l[1]) << 16);
            unsigned l23 = (unsigned)__bfloat16_as_ushort(l[2]) |
                           ((unsigned)__bfloat16_as_ushort(l[3]) << 16);
            *(uint2*)&Ahi[r][c4] = make_uint2(h01, h23);
            *(uint2*)&Alo[r][c4] = make_uint2(l01, l23);
        }
#pragma unroll
        for (int it = 0; it < 2; it++) {
            int idx = tid + it * 256;
            int kr  = idx >> 4;
            int nc4 = (idx & 15) * 4;
            float4 v = *(const float4*)&B[(size_t)(k0 + kr) * N + n0 + nc4];
            float f[4] = {v.x, v.y, v.z, v.w};
#pragma unroll
            for (int j = 0; j < 4; j++) {
                __nv_bfloat16 h = bf_hi(f[j]);
                Bthi[nc4 + j][kr] = h;
                Btlo[nc4 + j][kr] = bf_lo(f[j], h);
            }
        }
        __syncthreads();

#pragma unroll
        for (int ks = 0; ks < 2; ks++) {
            int kb = ks * 16;
            unsigned ah[2][4], al[2][4];
#pragma unroll
            for (int mf = 0; mf < 2; mf++) {
                int r0 = wm * 32 + mf * 16 + gid;
                ah[mf][0] = *(const unsigned*)&Ahi[r0    ][kb + 2 * tg];
                ah[mf][1] = *(const unsigned*)&Ahi[r0 + 8][kb + 2 * tg];
                ah[mf][2] = *(const unsigned*)&Ahi[r0    ][kb + 8 + 2 * tg];
                ah[mf][3] = *(const unsigned*)&Ahi[r0 + 8][kb + 8 + 2 * tg];
                al[mf][0] = *(const unsigned*)&Alo[r0    ][kb + 2 * tg];
                al[mf][1] = *(const unsigned*)&Alo[r0 + 8][kb + 2 * tg];
                al[mf][2] = *(const unsigned*)&Alo[r0    ][kb + 8 + 2 * tg];
                al[mf][3] = *(const unsigned*)&Alo[r0 + 8][kb + 8 + 2 * tg];
            }
            unsigned bh[4][2], bl[4][2];
#pragma unroll
            for (int nf = 0; nf < 4; nf++) {
                int n = wn * 32 + nf * 8 + gid;
                bh[nf][0] = *(const unsigned*)&Bthi[n][kb + 2 * tg];
                bh[nf][1] = *(const unsigned*)&Bthi[n][kb + 8 + 2 * tg];
                bl[nf][0] = *(const unsigned*)&Btlo[n][kb + 2 * tg];
                bl[nf][1] = *(const unsigned*)&Btlo[n][kb + 8 + 2 * tg];
            }
#pragma unroll
            for (int mf = 0; mf < 2; mf++)
#pragma unroll
                for (int nf = 0; nf < 4; nf++) {
                    mma16(acc[mf][nf], ah[mf], bh[nf]);
                    mma16(acc[mf][nf], ah[mf], bl[nf]);
                    mma16(acc[mf][nf], al[mf], bh[nf]);
                }
        }
        __syncthreads();
    }

#pragma unroll
    for (int mf = 0; mf < 2; mf++)
#pragma unroll
        for (int nf = 0; nf < 4; nf++) {
            int row = m0 + wm * 32 + mf * 16 + gid;
            int col = n0 + wn * 32 + nf * 8 + tg * 2;
            float v0 = acc[mf][nf][0], v1 = acc[mf][nf][1];
            float v2 = acc[mf][nf][2], v3 = acc[mf][nf][3];
            if (bias) {
                float b0 = bias[col], b1 = bias[col + 1];
                v0 += b0; v1 += b1; v2 += b0; v3 += b1;
            }
            if (relu) {
                v0 = fmaxf(v0, 0.f); v1 = fmaxf(v1, 0.f);
                v2 = fmaxf(v2, 0.f); v3 = fmaxf(v3, 0.f);
            }
            float2 w0 = {v0, v1}, w1 = {v2, v3};
            *(float2*)&C[(size_t)row * N + col] = w0;
            *(float2*)&C[(size_t)(row + 8) * N + col] = w1;
        }
}

// ---------------- scalar fp32 SGEMM (small matrices only) ----------------
#define BM 64
#define BN 64
#define BKK 16
__global__ __launch_bounds__(256)
void sgemm_kernel(const float* __restrict__ A, const float* __restrict__ B,
                  float* __restrict__ C, const float* __restrict__ bias,
                  int M, int N, int K, int relu) {
    __shared__ float As[BKK][BM + 4];
    __shared__ float Bs[BKK][BN];
    int tid = threadIdx.x;
    int m0 = blockIdx.y * BM;
    int n0 = blockIdx.x * BN;
    int tx = tid & 15, ty = tid >> 4;

    int arow = tid >> 2;
    int acol = (tid & 3) * 4;
    int brow = tid >> 4;
    int bcol = (tid & 15) * 4;

    float acc[4][4] = {};
    for (int k0 = 0; k0 < K; k0 += BKK) {
        float4 av = *(const float4*)&A[(size_t)(m0 + arow) * K + k0 + acol];
        As[acol + 0][arow] = av.x;
        As[acol + 1][arow] = av.y;
        As[acol + 2][arow] = av.z;
        As[acol + 3][arow] = av.w;
        float4 bv = *(const float4*)&B[(size_t)(k0 + brow) * N + n0 + bcol];
        *(float4*)&Bs[brow][bcol] = bv;
        __syncthreads();
#pragma unroll
        for (int kk = 0; kk < BKK; kk++) {
            float a[4], b[4];
            *(float4*)a = *(const float4*)&As[kk][ty * 4];
            *(float4*)b = *(const float4*)&Bs[kk][tx * 4];
#pragma unroll
            for (int i = 0; i < 4; i++)
#pragma unroll
                for (int j = 0; j < 4; j++)
                    acc[i][j] += a[i] * b[j];
        }
        __syncthreads();
    }
#pragma unroll
    for (int i = 0; i < 4; i++) {
        int m = m0 + ty * 4 + i;
#pragma unroll
        for (int j = 0; j < 4; j++) {
            int n = n0 + tx * 4 + j;
            float v = acc[i][j];
            if (bias) v += bias[n];
            if (relu) v = fmaxf(v, 0.f);
            C[(size_t)m * N + n] = v;
        }
    }
}

// ---------------- LSTM recurrence v5: balanced cluster j-split ------------
// 128 CTAs (64 clusters of 2). Rank = j-half, thread = (jl, kh).
// Changes vs v4b (all fp32-commutative -> bitwise-identical results):
//  * BOTH k-halves publish partials; epilogue split: kh finalizes rows
//    {2kh, 2kh+1} only (halved critical path, no idle half-CTA)
//  * xproj loads split 2 rows per thread
//  * pointer-bumped weight addressing (const LDG offsets)
#define LROWS 4
__global__ __launch_bounds__(256) __cluster_dims__(2, 1, 1)
void lstm_kernel(const float* __restrict__ xproj,
                 const float4* __restrict__ Whh4,
                 float* __restrict__ hN, float* __restrict__ cN) {
    cg::cluster_group cluster = cg::this_cluster();
    int tid = threadIdx.x;
    int jl = tid & 127;                 // local gate column
    int kh = tid >> 7;                  // k-half 0/1
    unsigned rank = cluster.block_rank();
    int gj = (int)rank * 128 + jl;      // global gate/h column
    int b0 = (blockIdx.x >> 1) * LROWS; // batch group
    int r0 = kh * 2;                    // rows this thread finalizes

    __shared__ float4 sh_h[2][HH];          // ping-pong full h, 8KB
    __shared__ float4 sh_p[2][LROWS][128];  // per-k-half partials, 16KB

    sh_h[0][tid] = make_float4(0.f, 0.f, 0.f, 0.f);
    sh_h[1][tid] = make_float4(0.f, 0.f, 0.f, 0.f);
    __syncthreads();
    cluster.sync();

    float4* peer_h = cluster.map_shared_rank(&sh_h[0][0], rank ^ 1u);

    const float4* wp0 = Whh4 + (size_t)(kh * 128) * HH + gj;
    float cA = 0.f, cB = 0.f;           // c for rows r0, r0+1

    int buf = 0;
    for (int t = 0; t < TT; t++) {
        // xproj loads for my 2 rows (in flight during the k-loop)
        float xg[2][4];
#pragma unroll
        for (int rr = 0; rr < 2; rr++) {
            size_t base = ((size_t)(b0 + r0 + rr) * SS + t) * G4H + gj;
            xg[rr][0] = xproj[base];
            xg[rr][1] = xproj[base + 256];
            xg[rr][2] = xproj[base + 512];
            xg[rr][3] = xproj[base + 768];
        }

        float ai[4] = {0.f,0.f,0.f,0.f}, af[4] = {0.f,0.f,0.f,0.f};
        float ag[4] = {0.f,0.f,0.f,0.f}, ao[4] = {0.f,0.f,0.f,0.f};
        const float4* hp = &sh_h[buf][kh * 128];
        const float4* wk = wp0;

        float4 wn[8];
#pragma unroll
        for (int u = 0; u < 8; u++) wn[u] = wk[u * HH];

#pragma unroll 1
        for (int k0 = 0; k0 < 128; k0 += 8) {
            float4 wc[8];
#pragma unroll
            for (int u = 0; u < 8; u++) wc[u] = wn[u];
            wk += 8 * HH;
            if (k0 + 8 < 128) {
#pragma unroll
                for (int u = 0; u < 8; u++) wn[u] = wk[u * HH];
            }
#pragma unroll
            for (int u = 0; u < 8; u++) {
                float4 h4 = hp[k0 + u];          // broadcast LDS.128
                ai[0] = fmaf(h4.x, wc[u].x, ai[0]);
                af[0] = fmaf(h4.x, wc[u].y, af[0]);
                ag[0] = fmaf(h4.x, wc[u].z, ag[0]);
                ao[0] = fmaf(h4.x, wc[u].w, ao[0]);
                ai[1] = fmaf(h4.y, wc[u].x, ai[1]);
                af[1] = fmaf(h4.y, wc[u].y, af[1]);
                ag[1] = fmaf(h4.y, wc[u].z, ag[1]);
                ao[1] = fmaf(h4.y, wc[u].w, ao[1]);
                ai[2] = fmaf(h4.z, wc[u].x, ai[2]);
                af[2] = fmaf(h4.z, wc[u].y, af[2]);
                ag[2] = fmaf(h4.z, wc[u].z, ag[2]);
                ao[2] = fmaf(h4.z, wc[u].w, ao[2]);
                ai[3] = fmaf(h4.w, wc[u].x, ai[3]);
                af[3] = fmaf(h4.w, wc[u].y, af[3]);
                ag[3] = fmaf(h4.w, wc[u].z, ag[3]);
                ao[3] = fmaf(h4.w, wc[u].w, ao[3]);
            }
        }

        // publish all-4-row partials for this k-half
#pragma unroll
        for (int r = 0; r < 4; r++)
            sh_p[kh][r][jl] = make_float4(ai[r], af[r], ag[r], ao[r]);
        __syncthreads();

        // finalize my 2 rows (own + peer partial is commutative -> exact)
        float hv[2];
#pragma unroll
        for (int rr = 0; rr < 2; rr++) {
            int ro = r0 + rr;
            float4 p = sh_p[kh ^ 1][ro][jl];
            float gi = (ai[ro] + p.x) + xg[rr][0];
            float gf = (af[ro] + p.y) + xg[rr][1];
            float gg = (ag[ro] + p.z) + xg[rr][2];
            float go = (ao[ro] + p.w) + xg[rr][3];
            float cprev = rr ? cB : cA;
            float cc = sigm(gf) * cprev + sigm(gi) * tanhf(gg);
            if (rr) cB = cc; else cA = cc;
            hv[rr] = sigm(go) * tanhf(cc);
        }

        // write my 8-byte half of the h slot (own + peer DSMEM)
        float2 hh = make_float2(hv[0], hv[1]);
        ((float2*)&sh_h[buf ^ 1][gj])[kh] = hh;
        ((float2*)&peer_h[(buf ^ 1) * HH + gj])[kh] = hh;

        cluster.sync();
        buf ^= 1;
    }

    // final: rows r0, r0+1 of column gj
    hN[(b0 + r0    ) * HH + gj] = ((float2*)&sh_h[buf][gj])[kh].x;
    hN[(b0 + r0 + 1) * HH + gj] = ((float2*)&sh_h[buf][gj])[kh].y;
    cN[(b0 + r0    ) * HH + gj] = cA;
    cN[(b0 + r0 + 1) * HH + gj] = cB;
}

// ---------------- tgt single-step LSTM (non-recurrent, parallel) ---------
__global__ __launch_bounds__(256)
void tgt_kernel(const float* __restrict__ xproj,
                const float* __restrict__ hproj,
                const float* __restrict__ cN) {
    int bt = blockIdx.x;
    int j  = threadIdx.x;
    int b = bt / TT, t = bt % TT;
    size_t base = ((size_t)b * SS + TT + t) * G4H + j;
    const float* hp = hproj + (size_t)b * G4H + j;
    float gi = xproj[base]       + hp[0];
    float gf = xproj[base + 256] + hp[256];
    float gg = xproj[base + 512] + hp[512];
    float go = xproj[base + 768] + hp[768];
    float cc = sigm(gf) * cN[b * HH + j] + sigm(gi) * tanhf(gg);
    g_htgt[(size_t)bt * HH + j] = sigm(go) * tanhf(cc);
}

// ---------------- final layer: out = sigmoid(z2 @ W3 + b3) ---------------
__global__ __launch_bounds__(128)
void final_kernel(const float* __restrict__ z2, const float* __restrict__ W3,
                  const float* __restrict__ b3, float* __restrict__ out) {
    int warp = threadIdx.x >> 5, lane = threadIdx.x & 31;
    int m = blockIdx.x * 4 + warp;
    if (m >= MT) return;
    const float* zr = z2 + (size_t)m * P2_;
    float s = 0.f;
#pragma unroll
    for (int q = 0; q < 4; q++) s = fmaf(zr[lane + q * 32], W3[lane + q * 32], s);
#pragma unroll
    for (int off = 16; off; off >>= 1) s += __shfl_xor_sync(0xFFFFFFFFu, s, off);
    if (lane == 0) out[m] = 1.f / (1.f + expf(-(s + b3[0])));
}

// ---------------- launch --------------------------------------------------
extern "C" void kernel_launch(void* const* d_in, const int* in_sizes, int n_in,
                              void* d_out, int out_size) {
    const int*   x    = (const int*)  d_in[0];
    const float* emb  = (const float*)d_in[1];
    const float* W_ih = (const float*)d_in[2];
    const float* W_hh = (const float*)d_in[3];
    const float* b_ih = (const float*)d_in[4];
    const float* b_hh = (const float*)d_in[5];
    const float* W1   = (const float*)d_in[6];
    const float* b1   = (const float*)d_in[7];
    const float* W2   = (const float*)d_in[8];
    const float* b2   = (const float*)d_in[9];
    const float* W3   = (const float*)d_in[10];
    const float* b3   = (const float*)d_in[11];
    float* out = (float*)d_out;

    float *e, *xproj, *WihT, *WhhT, *bsum, *hN, *cN, *hproj, *htgt, *z1, *z2;
    float4* Whh4;
    cudaGetSymbolAddress((void**)&e,     g_e);
    cudaGetSymbolAddress((void**)&xproj, g_xproj);
    cudaGetSymbolAddress((void**)&WihT,  g_WihT);
    cudaGetSymbolAddress((void**)&WhhT,  g_WhhT);
    cudaGetSymbolAddress((void**)&Whh4,  g_Whh4);
    cudaGetSymbolAddress((void**)&bsum,  g_bsum);
    cudaGetSymbolAddress((void**)&hN,    g_hN);
    cudaGetSymbolAddress((void**)&cN,    g_cN);
    cudaGetSymbolAddress((void**)&hproj, g_hproj);
    cudaGetSymbolAddress((void**)&htgt,  g_htgt);
    cudaGetSymbolAddress((void**)&z1,    g_z1);
    cudaGetSymbolAddress((void**)&z2,    g_z2);

    // 1) weight transposes + packed LSTM weights + bias combine
    prep_kernel<<<(HH * G4H + 255) / 256, 256>>>(W_ih, W_hh, b_ih, b_hh);

    // 2) embedding gather + mean
    gather_mean_kernel<<<BB * SS, EE>>>(x, emb);

    // 3) xproj = e @ W_ihT + bsum  — bf16-split tensor-core GEMM
    {
        dim3 grid(G4H / GBN, (BB * SS) / GBM);
        bf16_gemm<<<grid, 256>>>(e, WihT, xproj, bsum, BB * SS, G4H, EE, 0);
    }

    // 4) LSTM recurrence v5 (balanced cluster j-split)
    lstm_kernel<<<(BB / LROWS) * 2, 256>>>(xproj, Whh4, hN, cN);

    // 5) hproj = hN @ W_hhT  (small; exact fp32)
    {
        dim3 grid(G4H / BN, BB / BM);
        sgemm_kernel<<<grid, 256>>>(hN, WhhT, hproj, nullptr, BB, G4H, HH, 0);
    }

    // 6) tgt one-shot LSTM step
    tgt_kernel<<<MT, HH>>>(xproj, hproj, cN);

    // 7) MLP — bf16-split tensor-core GEMMs
    {
        dim3 grid(P1_ / GBN, MT / GBM);
        bf16_gemm<<<grid, 256>>>(htgt, W1, z1, b1, MT, P1_, HH, 1);
    }
    {
        dim3 grid(P2_ / GBN, MT / GBM);
        bf16_gemm<<<grid, 256>>>(z1, W2, z2, b2, MT, P2_, P1_, 1);
    }

    // 8) final dot + sigmoid
    final_kernel<<<MT / 4, 128>>>(z2, W3, b3, out);

    (void)in_sizes; (void)n_in; (void)out_size;
}